// round 1
// baseline (speedup 1.0000x reference)
#include <cuda_runtime.h>

// Problem constants
#define BATCH  2
#define SEQ    2048
#define DIN    64
#define NHEAD  16
#define DHEAD  64
#define HB     32          // NHEAD * BATCH
#define HD     1024        // NHEAD * DHEAD
#define NROWS  4096        // BATCH * SEQ
#define DO     1024

#define ATTN_ELEMS 134217728LL   // 32*2048*2048
#define OUT_ELEMS  4194304LL     // 2*2048*1024

// -------------------- scratch (no allocations allowed) --------------------
__device__ float g_Qh[HB * SEQ * DHEAD];   // [hb][n][d]
__device__ float g_Kh[HB * SEQ * DHEAD];
__device__ float g_Vh[HB * SEQ * DHEAD];
__device__ float g_m[HB * SEQ];            // row max
__device__ float g_l[HB * SEQ];            // row sum of exp
__device__ float g_oh[NROWS * HD];         // merged-head attention output [b*SEQ+n][h*64+d]
__device__ float g_attn_fb[134217728];     // fallback scratch if attn not part of d_out

// -------------------- fast FMA-only exp (avoids MUFU bottleneck) ----------
__device__ __forceinline__ float fexp(float x) {
    x = fmaxf(x, -80.0f);
    float t  = x * 1.4426950408889634f;       // x * log2(e)
    float fk = t + 12582912.0f;               // round-to-nearest via magic number
    float f  = t - (fk - 12582912.0f);        // frac in [-0.5, 0.5]
    int   n  = __float_as_int(fk) - 0x4B400000;
    float p  = 1.3333558146e-3f;              // 2^f Taylor/minimax, deg 5
    p = fmaf(p, f, 9.6181291e-3f);
    p = fmaf(p, f, 5.5504109e-2f);
    p = fmaf(p, f, 2.4022651e-1f);
    p = fmaf(p, f, 6.9314718e-1f);
    p = fmaf(p, f, 1.0f);
    return p * __int_as_float((n + 127) << 23);
}

// -------------------- kernel 1: QKV projection -----------------------------
// X:[B,SEQ,64] @ W:[64,1024] + b -> head-major Out[(h*B+b)*SEQ + n][64]
__global__ __launch_bounds__(256) void proj_kernel(
    const float* __restrict__ X, const float* __restrict__ W,
    const float* __restrict__ bias, float* __restrict__ Out) {
    __shared__ float Xs[64][65];
    __shared__ float Ws[64][65];
    int rt = blockIdx.x;        // 64 row tiles of 64
    int head = blockIdx.y;      // 16 heads = 64-col tiles
    int tid = threadIdx.x;

#pragma unroll
    for (int t = 0; t < 4; t++) {
        int f = tid + t * 256;
        int r = f >> 4, c = (f & 15) << 2;
        float4 xv = *(const float4*)(X + (size_t)(rt * 64 + r) * DIN + c);
        Xs[r][c] = xv.x; Xs[r][c + 1] = xv.y; Xs[r][c + 2] = xv.z; Xs[r][c + 3] = xv.w;
        float4 wv = *(const float4*)(W + (size_t)r * HD + head * 64 + c);
        Ws[r][c] = wv.x; Ws[r][c + 1] = wv.y; Ws[r][c + 2] = wv.z; Ws[r][c + 3] = wv.w;
    }
    __syncthreads();

    int ty = tid >> 4, tx = tid & 15;
    int r0 = ty * 4, c0 = tx * 4;
    float acc[4][4] = {};
#pragma unroll
    for (int k = 0; k < 64; k++) {
        float a[4], b[4];
#pragma unroll
        for (int i = 0; i < 4; i++) a[i] = Xs[r0 + i][k];
#pragma unroll
        for (int j = 0; j < 4; j++) b[j] = Ws[k][c0 + j];
#pragma unroll
        for (int i = 0; i < 4; i++)
#pragma unroll
            for (int j = 0; j < 4; j++) acc[i][j] = fmaf(a[i], b[j], acc[i][j]);
    }

    int bb = (rt * 64) / SEQ;
    int nbase = rt * 64 - bb * SEQ;
    float bv[4];
#pragma unroll
    for (int j = 0; j < 4; j++) bv[j] = bias[head * 64 + c0 + j];
#pragma unroll
    for (int i = 0; i < 4; i++) {
        float4 o;
        o.x = acc[i][0] + bv[0]; o.y = acc[i][1] + bv[1];
        o.z = acc[i][2] + bv[2]; o.w = acc[i][3] + bv[3];
        size_t row = (size_t)(head * BATCH + bb) * SEQ + nbase + r0 + i;
        *(float4*)(Out + row * DHEAD + c0) = o;
    }
}

// -------------------- kernel 2: scores + online row stats ------------------
// block = (hb, 128-row q tile); streams all 2048 keys in 128-key tiles.
// Writes S = QK^T / 8 to attn buffer; exact running max m and sum l.
__global__ __launch_bounds__(256) void scores_kernel(float* __restrict__ attn) {
    extern __shared__ float sm[];
    float (*Qt)[132] = (float(*)[132])sm;              // [64 dims][128 rows]
    float (*Kt)[132] = (float(*)[132])(sm + 64 * 132); // [64 dims][128 cols]
    float* m_s = sm + 2 * 64 * 132;                    // [128]
    float* l_s = m_s + 128;                            // [128]

    int hb = blockIdx.x, qt = blockIdx.y;
    int tid = threadIdx.x;
    int ty = tid >> 4, tx = tid & 15;
    int r0 = ty * 8, c0 = tx * 8;

    if (tid < 128) { m_s[tid] = -1e30f; l_s[tid] = 0.0f; }

    const float* Qp = g_Qh + ((size_t)hb * SEQ + qt * 128) * DHEAD;
#pragma unroll
    for (int t = 0; t < 8; t++) {
        int f = tid + t * 256;
        int r = f >> 4, c = (f & 15) << 2;
        float4 v = *(const float4*)(Qp + (size_t)r * DHEAD + c);
        Qt[c][r] = v.x; Qt[c + 1][r] = v.y; Qt[c + 2][r] = v.z; Qt[c + 3][r] = v.w;
    }

    float* attn_base = attn + (size_t)hb * SEQ * SEQ + (size_t)qt * 128 * SEQ;

    for (int kt = 0; kt < 16; kt++) {
        const float* Kp = g_Kh + ((size_t)hb * SEQ + kt * 128) * DHEAD;
#pragma unroll
        for (int t = 0; t < 8; t++) {
            int f = tid + t * 256;
            int r = f >> 4, c = (f & 15) << 2;
            float4 v = *(const float4*)(Kp + (size_t)r * DHEAD + c);
            Kt[c][r] = v.x; Kt[c + 1][r] = v.y; Kt[c + 2][r] = v.z; Kt[c + 3][r] = v.w;
        }
        __syncthreads();

        float acc[8][8] = {};
#pragma unroll
        for (int k = 0; k < 64; k++) {
            float a[8], b[8];
            *(float4*)&a[0] = *(const float4*)&Qt[k][r0];
            *(float4*)&a[4] = *(const float4*)&Qt[k][r0 + 4];
            *(float4*)&b[0] = *(const float4*)&Kt[k][c0];
            *(float4*)&b[4] = *(const float4*)&Kt[k][c0 + 4];
#pragma unroll
            for (int i = 0; i < 8; i++)
#pragma unroll
                for (int j = 0; j < 8; j++) acc[i][j] = fmaf(a[i], b[j], acc[i][j]);
        }
#pragma unroll
        for (int i = 0; i < 8; i++)
#pragma unroll
            for (int j = 0; j < 8; j++) acc[i][j] *= 0.125f;   // / sqrt(64)

        // online stats, per row (rows r0..r0+7 owned by the 16 lanes sharing ty)
#pragma unroll
        for (int i = 0; i < 8; i++) {
            float mx = acc[i][0];
#pragma unroll
            for (int j = 1; j < 8; j++) mx = fmaxf(mx, acc[i][j]);
#pragma unroll
            for (int off = 8; off; off >>= 1)
                mx = fmaxf(mx, __shfl_xor_sync(0xffffffffu, mx, off));
            float mold = m_s[r0 + i];
            float mnew = fmaxf(mold, mx);
            float se = 0.0f;
#pragma unroll
            for (int j = 0; j < 8; j++) se += fexp(acc[i][j] - mnew);
#pragma unroll
            for (int off = 8; off; off >>= 1)
                se += __shfl_xor_sync(0xffffffffu, se, off);
            if (tx == 0) {
                l_s[r0 + i] = l_s[r0 + i] * fexp(mold - mnew) + se;
                m_s[r0 + i] = mnew;
            }
        }

        // store raw scaled scores
#pragma unroll
        for (int i = 0; i < 8; i++) {
            float4 w0, w1;
            w0.x = acc[i][0]; w0.y = acc[i][1]; w0.z = acc[i][2]; w0.w = acc[i][3];
            w1.x = acc[i][4]; w1.y = acc[i][5]; w1.z = acc[i][6]; w1.w = acc[i][7];
            float* p = attn_base + (size_t)(r0 + i) * SEQ + kt * 128 + c0;
            *(float4*)p = w0;
            *(float4*)(p + 4) = w1;
        }
        __syncthreads();
    }

    if (tid < 128) {
        g_m[hb * SEQ + qt * 128 + tid] = m_s[tid];
        g_l[hb * SEQ + qt * 128 + tid] = l_s[tid];
    }
}

// -------------------- kernel 3: normalize attn + PV ------------------------
// reads raw S, writes attn = exp(S-m)/l in place, accumulates O = attn @ V
__global__ __launch_bounds__(256) void pv_kernel(float* __restrict__ attn) {
    extern __shared__ float sm[];
    float (*Pt)[132] = (float(*)[132])sm;                      // [64 keys][128 rows]
    float (*Vs)[68]  = (float(*)[68])(sm + 64 * 132);          // [64 keys][64 dims]
    float* mrow = sm + 64 * 132 + 64 * 68;                     // [128]
    float* lrow = mrow + 128;                                  // [128] (1/l)

    int hb = blockIdx.x, qt = blockIdx.y;
    int tid = threadIdx.x;
    int ty = tid >> 4, tx = tid & 15;
    int r0 = ty * 8, d0 = tx * 4;

    if (tid < 128) {
        mrow[tid] = g_m[hb * SEQ + qt * 128 + tid];
        lrow[tid] = 1.0f / g_l[hb * SEQ + qt * 128 + tid];
    }
    __syncthreads();

    float acc[8][4] = {};
    float* arow = attn + (size_t)hb * SEQ * SEQ + (size_t)qt * 128 * SEQ;

    for (int kt = 0; kt < 32; kt++) {          // 64 keys per sub-tile
#pragma unroll
        for (int t = 0; t < 8; t++) {
            int f = tid + t * 256;
            int r = f >> 4, c = (f & 15) << 2;
            float* p = arow + (size_t)r * SEQ + kt * 64 + c;
            float4 v = *(float4*)p;
            float mm = mrow[r], il = lrow[r];
            v.x = fexp(v.x - mm) * il;
            v.y = fexp(v.y - mm) * il;
            v.z = fexp(v.z - mm) * il;
            v.w = fexp(v.w - mm) * il;
            *(float4*)p = v;
            Pt[c][r] = v.x; Pt[c + 1][r] = v.y; Pt[c + 2][r] = v.z; Pt[c + 3][r] = v.w;
        }
        const float* Vp = g_Vh + ((size_t)hb * SEQ + kt * 64) * DHEAD;
#pragma unroll
        for (int t = 0; t < 4; t++) {
            int f = tid + t * 256;
            int r = f >> 4, c = (f & 15) << 2;
            *(float4*)&Vs[r][c] = *(const float4*)(Vp + (size_t)r * DHEAD + c);
        }
        __syncthreads();

#pragma unroll
        for (int k = 0; k < 64; k++) {
            float a[8], b[4];
            *(float4*)&a[0] = *(const float4*)&Pt[k][r0];
            *(float4*)&a[4] = *(const float4*)&Pt[k][r0 + 4];
            *(float4*)&b[0] = *(const float4*)&Vs[k][d0];
#pragma unroll
            for (int i = 0; i < 8; i++)
#pragma unroll
                for (int j = 0; j < 4; j++) acc[i][j] = fmaf(a[i], b[j], acc[i][j]);
        }
        __syncthreads();
    }

    int h = hb >> 1;        // hb = h*BATCH + b
    int bb = hb & 1;
#pragma unroll
    for (int i = 0; i < 8; i++) {
        int n = qt * 128 + r0 + i;
        float4 o;
        o.x = acc[i][0]; o.y = acc[i][1]; o.z = acc[i][2]; o.w = acc[i][3];
        *(float4*)(g_oh + ((size_t)bb * SEQ + n) * HD + h * 64 + d0) = o;
    }
}

// -------------------- kernel 4: output projection --------------------------
// out[4096,1024] = g_oh[4096,1024] @ Wo[1024,1024] + bo
__global__ __launch_bounds__(256) void oproj_kernel(
    const float* __restrict__ Wo, const float* __restrict__ bo,
    float* __restrict__ out) {
    __shared__ float At[32][132];   // [k][row]
    __shared__ float Bs[32][132];   // [k][col]
    int rt = blockIdx.x, ct = blockIdx.y;
    int tid = threadIdx.x;
    int ty = tid >> 4, tx = tid & 15;
    int r0 = ty * 8, c0 = tx * 8;

    float acc[8][8] = {};
    for (int kt = 0; kt < 32; kt++) {
#pragma unroll
        for (int t = 0; t < 4; t++) {
            int f = tid + t * 256;
            int r = f >> 3, c = (f & 7) << 2;       // A chunk 128x32
            float4 v = *(const float4*)(g_oh + (size_t)(rt * 128 + r) * HD + kt * 32 + c);
            At[c][r] = v.x; At[c + 1][r] = v.y; At[c + 2][r] = v.z; At[c + 3][r] = v.w;
            int rb = f >> 5, cb = (f & 31) << 2;    // B chunk 32x128
            *(float4*)&Bs[rb][cb] =
                *(const float4*)(Wo + (size_t)(kt * 32 + rb) * DO + ct * 128 + cb);
        }
        __syncthreads();
#pragma unroll
        for (int k = 0; k < 32; k++) {
            float a[8], b[8];
            *(float4*)&a[0] = *(const float4*)&At[k][r0];
            *(float4*)&a[4] = *(const float4*)&At[k][r0 + 4];
            *(float4*)&b[0] = *(const float4*)&Bs[k][c0];
            *(float4*)&b[4] = *(const float4*)&Bs[k][c0 + 4];
#pragma unroll
            for (int i = 0; i < 8; i++)
#pragma unroll
                for (int j = 0; j < 8; j++) acc[i][j] = fmaf(a[i], b[j], acc[i][j]);
        }
        __syncthreads();
    }

    float bv[8];
#pragma unroll
    for (int j = 0; j < 8; j++) bv[j] = bo[ct * 128 + c0 + j];
#pragma unroll
    for (int i = 0; i < 8; i++) {
        size_t row = (size_t)(rt * 128 + r0 + i);
        float4 o0, o1;
        o0.x = acc[i][0] + bv[0]; o0.y = acc[i][1] + bv[1];
        o0.z = acc[i][2] + bv[2]; o0.w = acc[i][3] + bv[3];
        o1.x = acc[i][4] + bv[4]; o1.y = acc[i][5] + bv[5];
        o1.z = acc[i][6] + bv[6]; o1.w = acc[i][7] + bv[7];
        float* p = out + row * DO + ct * 128 + c0;
        *(float4*)p = o0;
        *(float4*)(p + 4) = o1;
    }
}

// -------------------- launch -----------------------------------------------
extern "C" void kernel_launch(void* const* d_in, const int* in_sizes, int n_in,
                              void* d_out, int out_size) {
    const float* q  = (const float*)d_in[0];
    const float* k  = (const float*)d_in[1];
    const float* v  = (const float*)d_in[2];
    const float* Wq = (const float*)d_in[3];
    const float* bq = (const float*)d_in[4];
    const float* Wk = (const float*)d_in[5];
    const float* bk = (const float*)d_in[6];
    const float* Wv = (const float*)d_in[7];
    const float* bv = (const float*)d_in[8];
    const float* Wo = (const float*)d_in[9];
    const float* bo = (const float*)d_in[10];
    (void)in_sizes; (void)n_in;

    long long osz = (long long)out_size;
    float* attn = nullptr;
    float* out  = nullptr;
    if (osz >= ATTN_ELEMS + OUT_ELEMS) {
        attn = (float*)d_out;
        out  = (float*)d_out + ATTN_ELEMS;
    } else if (osz >= ATTN_ELEMS) {
        attn = (float*)d_out;
    } else {
        out = (float*)d_out;
    }
    if (!attn) cudaGetSymbolAddress((void**)&attn, g_attn_fb);

    float *Qh, *Kh, *Vh;
    cudaGetSymbolAddress((void**)&Qh, g_Qh);
    cudaGetSymbolAddress((void**)&Kh, g_Kh);
    cudaGetSymbolAddress((void**)&Vh, g_Vh);

    const int SC_SMEM = (2 * 64 * 132 + 256) * 4;            // 68608 B
    const int PV_SMEM = (64 * 132 + 64 * 68 + 256) * 4;      // 52224 B
    cudaFuncSetAttribute(scores_kernel, cudaFuncAttributeMaxDynamicSharedMemorySize, SC_SMEM);
    cudaFuncSetAttribute(pv_kernel, cudaFuncAttributeMaxDynamicSharedMemorySize, PV_SMEM);

    dim3 blk(256);
    proj_kernel<<<dim3(64, 16), blk>>>(q, Wq, bq, Qh);
    proj_kernel<<<dim3(64, 16), blk>>>(k, Wk, bk, Kh);
    proj_kernel<<<dim3(64, 16), blk>>>(v, Wv, bv, Vh);
    scores_kernel<<<dim3(HB, 16), blk, SC_SMEM>>>(attn);
    pv_kernel<<<dim3(HB, 16), blk, PV_SMEM>>>(attn);
    if (out) oproj_kernel<<<dim3(32, 8), blk>>>(Wo, bo, out);
}

// round 5
// speedup vs baseline: 1.5548x; 1.5548x over previous
#include <cuda_runtime.h>
#include <cuda_bf16.h>
#include <cstdint>

// Problem constants
#define BATCH  2
#define SEQ    2048
#define DIN    64
#define NHEAD  16
#define DHEAD  64
#define HB     32
#define HD     1024
#define NROWS  4096
#define DO     1024

#define ATTN_ELEMS 134217728LL
#define OUT_ELEMS  4194304LL

// fold 1/sqrt(64) and log2(e): scores kept in log2 domain
#define SCL (0.125f * 1.4426950408889634f)

// -------------------- scratch --------------------
__device__ float g_Qh[HB * SEQ * DHEAD];
__device__ float g_Kh[HB * SEQ * DHEAD];
__device__ float g_Vh[HB * SEQ * DHEAD];
__device__ float g_m[HB * SEQ];
__device__ float g_l[HB * SEQ];
__device__ float g_oh[NROWS * HD];
__device__ float g_attn_fb[134217728];

// -------------------- helpers --------------------
__device__ __forceinline__ uint32_t su32(const void* p) {
    uint32_t a;
    asm("{ .reg .u64 t; cvta.to.shared.u64 t, %1; cvt.u32.u64 %0, t; }" : "=r"(a) : "l"(p));
    return a;
}
__device__ __forceinline__ float ex2f(float x) {
    float y;
    asm("ex2.approx.f32 %0, %1;" : "=f"(y) : "f"(x));
    return y;
}
__device__ __forceinline__ void tf32split(float x, float& h, float& l) {
    asm("cvt.rna.tf32.f32 %0, %1;" : "=f"(h) : "f"(x));
    float r = x - h;
    asm("cvt.rna.tf32.f32 %0, %1;" : "=f"(l) : "f"(r));
}
__device__ __forceinline__ uint32_t pack2bf(float a, float b) {
    __nv_bfloat162 t = __floats2bfloat162_rn(a, b);
    return *(uint32_t*)&t;
}
__device__ __forceinline__ void mma_tf32(float* c, const uint32_t* a, const uint32_t* b) {
    asm volatile("mma.sync.aligned.m16n8k8.row.col.f32.tf32.tf32.f32 "
                 "{%0,%1,%2,%3}, {%4,%5,%6,%7}, {%8,%9}, {%0,%1,%2,%3};"
                 : "+f"(c[0]), "+f"(c[1]), "+f"(c[2]), "+f"(c[3])
                 : "r"(a[0]), "r"(a[1]), "r"(a[2]), "r"(a[3]), "r"(b[0]), "r"(b[1]));
}
__device__ __forceinline__ void mma_bf16(float* c, const uint32_t* a, const uint32_t* b) {
    asm volatile("mma.sync.aligned.m16n8k16.row.col.f32.bf16.bf16.f32 "
                 "{%0,%1,%2,%3}, {%4,%5,%6,%7}, {%8,%9}, {%0,%1,%2,%3};"
                 : "+f"(c[0]), "+f"(c[1]), "+f"(c[2]), "+f"(c[3])
                 : "r"(a[0]), "r"(a[1]), "r"(a[2]), "r"(a[3]), "r"(b[0]), "r"(b[1]));
}
__device__ __forceinline__ void ldmA(uint32_t* r, uint32_t addr) {
    asm volatile("ldmatrix.sync.aligned.m8n8.x4.shared.b16 {%0,%1,%2,%3}, [%4];"
                 : "=r"(r[0]), "=r"(r[1]), "=r"(r[2]), "=r"(r[3]) : "r"(addr));
}
__device__ __forceinline__ void ldmB(uint32_t* r, uint32_t addr) {
    asm volatile("ldmatrix.sync.aligned.m8n8.x2.trans.shared.b16 {%0,%1}, [%2];"
                 : "=r"(r[0]), "=r"(r[1]) : "r"(addr));
}

// ==================== kernel 1: QKV projection (FMA) ====================
__global__ __launch_bounds__(256) void proj_kernel(
    const float* __restrict__ X, const float* __restrict__ W,
    const float* __restrict__ bias, float* __restrict__ Out) {
    __shared__ float Xs[64][65];
    __shared__ float Ws[64][65];
    int rt = blockIdx.x, head = blockIdx.y, tid = threadIdx.x;
#pragma unroll
    for (int t = 0; t < 4; t++) {
        int f = tid + t * 256;
        int r = f >> 4, c = (f & 15) << 2;
        float4 xv = *(const float4*)(X + (size_t)(rt * 64 + r) * DIN + c);
        Xs[r][c] = xv.x; Xs[r][c + 1] = xv.y; Xs[r][c + 2] = xv.z; Xs[r][c + 3] = xv.w;
        float4 wv = *(const float4*)(W + (size_t)r * HD + head * 64 + c);
        Ws[r][c] = wv.x; Ws[r][c + 1] = wv.y; Ws[r][c + 2] = wv.z; Ws[r][c + 3] = wv.w;
    }
    __syncthreads();
    int ty = tid >> 4, tx = tid & 15;
    int r0 = ty * 4, c0 = tx * 4;
    float acc[4][4] = {};
#pragma unroll
    for (int k = 0; k < 64; k++) {
        float a[4], b[4];
#pragma unroll
        for (int i = 0; i < 4; i++) a[i] = Xs[r0 + i][k];
#pragma unroll
        for (int j = 0; j < 4; j++) b[j] = Ws[k][c0 + j];
#pragma unroll
        for (int i = 0; i < 4; i++)
#pragma unroll
            for (int j = 0; j < 4; j++) acc[i][j] = fmaf(a[i], b[j], acc[i][j]);
    }
    int bb = (rt * 64) / SEQ;
    int nbase = rt * 64 - bb * SEQ;
    float bv[4];
#pragma unroll
    for (int j = 0; j < 4; j++) bv[j] = bias[head * 64 + c0 + j];
#pragma unroll
    for (int i = 0; i < 4; i++) {
        float4 o;
        o.x = acc[i][0] + bv[0]; o.y = acc[i][1] + bv[1];
        o.z = acc[i][2] + bv[2]; o.w = acc[i][3] + bv[3];
        size_t row = (size_t)(head * BATCH + bb) * SEQ + nbase + r0 + i;
        *(float4*)(Out + row * DHEAD + c0) = o;
    }
}

// ==================== kernel 2: scores via 3xTF32 mma.sync ====================
// smem (floats): Qh[128*68], Ql[128*68], Kbuf0{hi,lo}, Kbuf1{hi,lo}
#define SC_BS 8704               // 128*68 floats
#define SC_SMEM_BYTES (6 * SC_BS * 4)   // 208896

__global__ __launch_bounds__(256, 1) void scores_mma_kernel(float* __restrict__ attn) {
    extern __shared__ float sm[];
    float* Qh_s = sm;
    float* Ql_s = sm + SC_BS;

    int tid = threadIdx.x, lane = tid & 31, w = tid >> 5;
    int g = lane >> 2, tg = lane & 3;
    int hb = blockIdx.x, qt = blockIdx.y;
    int r1 = w * 16 + g;

    // ---- load Q (scaled to log2 domain, tf32 split) ----
    const float* Qp = g_Qh + ((size_t)hb * SEQ + qt * 128) * DHEAD;
#pragma unroll
    for (int t = 0; t < 8; t++) {
        int f = tid + t * 256;
        int r = f >> 4, c = (f & 15) << 2;
        float4 v = *(const float4*)(Qp + (size_t)r * DHEAD + c);
        v.x *= SCL; v.y *= SCL; v.z *= SCL; v.w *= SCL;
        float4 h4, l4;
        tf32split(v.x, h4.x, l4.x); tf32split(v.y, h4.y, l4.y);
        tf32split(v.z, h4.z, l4.z); tf32split(v.w, h4.w, l4.w);
        *(float4*)(Qh_s + r * 68 + c) = h4;
        *(float4*)(Ql_s + r * 68 + c) = l4;
    }

    // ---- prologue: K tile 0 -> buf0 ----
    {
        const float* Kp = g_Kh + ((size_t)hb * SEQ) * DHEAD;
        float* Dh = sm + 2 * SC_BS;
        float* Dl = Dh + SC_BS;
#pragma unroll
        for (int t = 0; t < 8; t++) {
            int f = tid + t * 256;
            int r = f >> 4, c = (f & 15) << 2;
            float4 v = *(const float4*)(Kp + (size_t)r * DHEAD + c);
            float4 h4, l4;
            tf32split(v.x, h4.x, l4.x); tf32split(v.y, h4.y, l4.y);
            tf32split(v.z, h4.z, l4.z); tf32split(v.w, h4.w, l4.w);
            *(float4*)(Dh + r * 68 + c) = h4;
            *(float4*)(Dl + r * 68 + c) = l4;
        }
    }
    __syncthreads();

    float m1 = -1e30f, l1 = 0.f, m2 = -1e30f, l2 = 0.f;
    float* Tbase = attn + (size_t)hb * SEQ * SEQ + (size_t)(qt * 128) * SEQ;

    for (int kt = 0; kt < 16; kt++) {
        // prefetch next K tile into registers
        float4 pre[8];
        if (kt < 15) {
            const float* Kp = g_Kh + ((size_t)hb * SEQ + (kt + 1) * 128) * DHEAD;
#pragma unroll
            for (int t = 0; t < 8; t++) {
                int f = tid + t * 256;
                int r = f >> 4, c = (f & 15) << 2;
                pre[t] = *(const float4*)(Kp + (size_t)r * DHEAD + c);
            }
        }
        const float* Kh_s = sm + 2 * SC_BS + (kt & 1) * 2 * SC_BS;
        const float* Kl_s = Kh_s + SC_BS;

        float C[16][4];
#pragma unroll
        for (int j = 0; j < 16; j++) { C[j][0] = C[j][1] = C[j][2] = C[j][3] = 0.f; }

#pragma unroll
        for (int ks = 0; ks < 8; ks++) {
            int c0 = ks * 8 + tg;
            uint32_t aH[4], aL[4];
            aH[0] = __float_as_uint(Qh_s[r1 * 68 + c0]);
            aH[1] = __float_as_uint(Qh_s[(r1 + 8) * 68 + c0]);
            aH[2] = __float_as_uint(Qh_s[r1 * 68 + c0 + 4]);
            aH[3] = __float_as_uint(Qh_s[(r1 + 8) * 68 + c0 + 4]);
            aL[0] = __float_as_uint(Ql_s[r1 * 68 + c0]);
            aL[1] = __float_as_uint(Ql_s[(r1 + 8) * 68 + c0]);
            aL[2] = __float_as_uint(Ql_s[r1 * 68 + c0 + 4]);
            aL[3] = __float_as_uint(Ql_s[(r1 + 8) * 68 + c0 + 4]);
#pragma unroll
            for (int j = 0; j < 16; j++) {
                int kc = j * 8 + g;      // key index
                int kr = ks * 8 + tg;    // dim index
                uint32_t bH[2], bL[2];
                bH[0] = __float_as_uint(Kh_s[kc * 68 + kr]);
                bH[1] = __float_as_uint(Kh_s[kc * 68 + kr + 4]);
                bL[0] = __float_as_uint(Kl_s[kc * 68 + kr]);
                bL[1] = __float_as_uint(Kl_s[kc * 68 + kr + 4]);
                mma_tf32(C[j], aH, bH);
                mma_tf32(C[j], aH, bL);
                mma_tf32(C[j], aL, bH);
            }
        }

        // online row stats (rows r1 via C[j][0..1], r1+8 via C[j][2..3])
        float mxa = C[0][0], mxb = C[0][2];
#pragma unroll
        for (int j = 0; j < 16; j++) {
            mxa = fmaxf(mxa, fmaxf(C[j][0], C[j][1]));
            mxb = fmaxf(mxb, fmaxf(C[j][2], C[j][3]));
        }
        mxa = fmaxf(mxa, __shfl_xor_sync(0xffffffffu, mxa, 1));
        mxa = fmaxf(mxa, __shfl_xor_sync(0xffffffffu, mxa, 2));
        mxb = fmaxf(mxb, __shfl_xor_sync(0xffffffffu, mxb, 1));
        mxb = fmaxf(mxb, __shfl_xor_sync(0xffffffffu, mxb, 2));
        float M1 = fmaxf(m1, mxa), M2 = fmaxf(m2, mxb);
        float sa = 0.f, sb2 = 0.f;
#pragma unroll
        for (int j = 0; j < 16; j++) {
            sa  += ex2f(C[j][0] - M1) + ex2f(C[j][1] - M1);
            sb2 += ex2f(C[j][2] - M2) + ex2f(C[j][3] - M2);
        }
        sa  += __shfl_xor_sync(0xffffffffu, sa, 1);
        sa  += __shfl_xor_sync(0xffffffffu, sa, 2);
        sb2 += __shfl_xor_sync(0xffffffffu, sb2, 1);
        sb2 += __shfl_xor_sync(0xffffffffu, sb2, 2);
        l1 = l1 * ex2f(m1 - M1) + sa;  m1 = M1;
        l2 = l2 * ex2f(m2 - M2) + sb2; m2 = M2;

        // store T (log2-domain raw scores)
        float* p1 = Tbase + (size_t)r1 * SEQ + kt * 128 + 2 * tg;
        float* p2 = Tbase + (size_t)(r1 + 8) * SEQ + kt * 128 + 2 * tg;
#pragma unroll
        for (int j = 0; j < 16; j++) {
            *(float2*)(p1 + j * 8) = make_float2(C[j][0], C[j][1]);
            *(float2*)(p2 + j * 8) = make_float2(C[j][2], C[j][3]);
        }

        // split + store the prefetched tile into the other buffer
        if (kt < 15) {
            float* Dh = sm + 2 * SC_BS + ((kt + 1) & 1) * 2 * SC_BS;
            float* Dl = Dh + SC_BS;
#pragma unroll
            for (int t = 0; t < 8; t++) {
                int f = tid + t * 256;
                int r = f >> 4, c = (f & 15) << 2;
                float4 v = pre[t];
                float4 h4, l4;
                tf32split(v.x, h4.x, l4.x); tf32split(v.y, h4.y, l4.y);
                tf32split(v.z, h4.z, l4.z); tf32split(v.w, h4.w, l4.w);
                *(float4*)(Dh + r * 68 + c) = h4;
                *(float4*)(Dl + r * 68 + c) = l4;
            }
        }
        __syncthreads();
    }

    if (tg == 0) {
        int base = hb * SEQ + qt * 128;
        g_m[base + r1] = m1;      g_l[base + r1] = l1;
        g_m[base + r1 + 8] = m2;  g_l[base + r1 + 8] = l2;
    }
}

// ==================== kernel 3: normalize + PV via bf16-3x mma.sync ====================
// smem bytes: AsH 0(18432) AsL 18432 VsH 36864(9216) VsL 46080 msm 55296(512) ilsm 55808(512)
#define PV_SMEM_BYTES 56320

__global__ __launch_bounds__(256, 1) void pv_mma_kernel(float* __restrict__ attn) {
    extern __shared__ char smc[];
    __nv_bfloat16* AsH = (__nv_bfloat16*)(smc);
    __nv_bfloat16* AsL = (__nv_bfloat16*)(smc + 18432);
    __nv_bfloat16* VsH = (__nv_bfloat16*)(smc + 36864);
    __nv_bfloat16* VsL = (__nv_bfloat16*)(smc + 46080);
    float* msm  = (float*)(smc + 55296);
    float* ilsm = (float*)(smc + 55808);
    uint32_t sb = su32(smc);

    int tid = threadIdx.x, lane = tid & 31, w = tid >> 5;
    int g = lane >> 2, tg = lane & 3;
    int hb = blockIdx.x, qt = blockIdx.y;

    if (tid < 128) {
        msm[tid] = g_m[hb * SEQ + qt * 128 + tid];
        ilsm[tid] = 1.0f / g_l[hb * SEQ + qt * 128 + tid];
    }
    __syncthreads();

    float C[8][4];
#pragma unroll
    for (int j = 0; j < 8; j++) { C[j][0] = C[j][1] = C[j][2] = C[j][3] = 0.f; }

    float* arow = attn + (size_t)hb * SEQ * SEQ + (size_t)(qt * 128) * SEQ;

    for (int kc = 0; kc < 32; kc++) {
        // normalize attn chunk in place, stage bf16 hi/lo
#pragma unroll
        for (int t = 0; t < 8; t++) {
            int f = tid + t * 256;
            int r = f >> 4, c = (f & 15) << 2;
            float* p = arow + (size_t)r * SEQ + kc * 64 + c;
            float4 v = *(float4*)p;
            float mm = msm[r], il = ilsm[r];
            v.x = ex2f(v.x - mm) * il;
            v.y = ex2f(v.y - mm) * il;
            v.z = ex2f(v.z - mm) * il;
            v.w = ex2f(v.w - mm) * il;
            *(float4*)p = v;
            float hx = __bfloat162float(__float2bfloat16_rn(v.x));
            float hy = __bfloat162float(__float2bfloat16_rn(v.y));
            float hz = __bfloat162float(__float2bfloat16_rn(v.z));
            float hw = __bfloat162float(__float2bfloat16_rn(v.w));
            uint2 hp, lp;
            hp.x = pack2bf(hx, hy); hp.y = pack2bf(hz, hw);
            lp.x = pack2bf(v.x - hx, v.y - hy); lp.y = pack2bf(v.z - hz, v.w - hw);
            *(uint2*)(AsH + r * 72 + c) = hp;
            *(uint2*)(AsL + r * 72 + c) = lp;
        }
        // V chunk
        const float* Vp = g_Vh + ((size_t)hb * SEQ + kc * 64) * DHEAD;
#pragma unroll
        for (int t = 0; t < 4; t++) {
            int f = tid + t * 256;
            int kk = f >> 4, dd = (f & 15) << 2;
            float4 v = *(const float4*)(Vp + (size_t)kk * DHEAD + dd);
            float hx = __bfloat162float(__float2bfloat16_rn(v.x));
            float hy = __bfloat162float(__float2bfloat16_rn(v.y));
            float hz = __bfloat162float(__float2bfloat16_rn(v.z));
            float hw = __bfloat162float(__float2bfloat16_rn(v.w));
            uint2 hp, lp;
            hp.x = pack2bf(hx, hy); hp.y = pack2bf(hz, hw);
            lp.x = pack2bf(v.x - hx, v.y - hy); lp.y = pack2bf(v.z - hz, v.w - hw);
            *(uint2*)(VsH + kk * 72 + dd) = hp;
            *(uint2*)(VsL + kk * 72 + dd) = lp;
        }
        __syncthreads();

        uint32_t aHf[4][4], aLf[4][4];
        int arw = w * 16 + (lane & 15);
        int acl = ((lane >> 4) & 1) * 8;
#pragma unroll
        for (int s = 0; s < 4; s++) {
            uint32_t off = (uint32_t)((arw * 72 + s * 16 + acl) * 2);
            ldmA(aHf[s], sb + 0 + off);
            ldmA(aLf[s], sb + 18432 + off);
        }
#pragma unroll
        for (int j = 0; j < 8; j++) {
#pragma unroll
            for (int s = 0; s < 4; s++) {
                uint32_t bH[2], bL[2];
                uint32_t off = (uint32_t)(((s * 16 + (lane & 15)) * 72 + j * 8) * 2);
                ldmB(bH, sb + 36864 + off);
                ldmB(bL, sb + 46080 + off);
                mma_bf16(C[j], aHf[s], bH);
                mma_bf16(C[j], aHf[s], bL);
                mma_bf16(C[j], aLf[s], bH);
            }
        }
        __syncthreads();
    }

    int h = hb >> 1, bb = hb & 1;
    int r1 = w * 16 + g;
    float* o1 = g_oh + ((size_t)(bb * SEQ + qt * 128 + r1)) * HD + h * 64 + 2 * tg;
    float* o2 = o1 + 8 * HD;
#pragma unroll
    for (int j = 0; j < 8; j++) {
        *(float2*)(o1 + j * 8) = make_float2(C[j][0], C[j][1]);
        *(float2*)(o2 + j * 8) = make_float2(C[j][2], C[j][3]);
    }
}

// ==================== kernel 4: out projection via bf16-3x mma.sync ====================
// smem bytes: AH 0(18432) AL 18432 BH 36864(17408) BL 54272(17408); total 71680
#define OP_SMEM_BYTES 71680

__global__ __launch_bounds__(256, 1) void oproj_mma_kernel(
    const float* __restrict__ Wo, const float* __restrict__ bo, float* __restrict__ out) {
    extern __shared__ char smc[];
    __nv_bfloat16* AH = (__nv_bfloat16*)(smc);
    __nv_bfloat16* AL = (__nv_bfloat16*)(smc + 18432);
    __nv_bfloat16* BH = (__nv_bfloat16*)(smc + 36864);
    __nv_bfloat16* BL = (__nv_bfloat16*)(smc + 54272);
    uint32_t sb = su32(smc);

    int tid = threadIdx.x, lane = tid & 31, w = tid >> 5;
    int g = lane >> 2, tg = lane & 3;
    int rt = blockIdx.x, ct = blockIdx.y;

    float C[16][4];
#pragma unroll
    for (int j = 0; j < 16; j++) { C[j][0] = C[j][1] = C[j][2] = C[j][3] = 0.f; }

    for (int kc = 0; kc < 16; kc++) {
        // A = g_oh chunk [128][64]
#pragma unroll
        for (int t = 0; t < 8; t++) {
            int f = tid + t * 256;
            int r = f >> 4, c = (f & 15) << 2;
            float4 v = *(const float4*)(g_oh + (size_t)(rt * 128 + r) * HD + kc * 64 + c);
            float hx = __bfloat162float(__float2bfloat16_rn(v.x));
            float hy = __bfloat162float(__float2bfloat16_rn(v.y));
            float hz = __bfloat162float(__float2bfloat16_rn(v.z));
            float hw = __bfloat162float(__float2bfloat16_rn(v.w));
            uint2 hp, lp;
            hp.x = pack2bf(hx, hy); hp.y = pack2bf(hz, hw);
            lp.x = pack2bf(v.x - hx, v.y - hy); lp.y = pack2bf(v.z - hz, v.w - hw);
            *(uint2*)(AH + r * 72 + c) = hp;
            *(uint2*)(AL + r * 72 + c) = lp;
        }
        // B = Wo chunk [64][128]
#pragma unroll
        for (int t = 0; t < 8; t++) {
            int f = tid + t * 256;
            int kk = f >> 5, nn = (f & 31) << 2;
            float4 v = *(const float4*)(Wo + (size_t)(kc * 64 + kk) * DO + ct * 128 + nn);
            float hx = __bfloat162float(__float2bfloat16_rn(v.x));
            float hy = __bfloat162float(__float2bfloat16_rn(v.y));
            float hz = __bfloat162float(__float2bfloat16_rn(v.z));
            float hw = __bfloat162float(__float2bfloat16_rn(v.w));
            uint2 hp, lp;
            hp.x = pack2bf(hx, hy); hp.y = pack2bf(hz, hw);
            lp.x = pack2bf(v.x - hx, v.y - hy); lp.y = pack2bf(v.z - hz, v.w - hw);
            *(uint2*)(BH + kk * 136 + nn) = hp;
            *(uint2*)(BL + kk * 136 + nn) = lp;
        }
        __syncthreads();

        uint32_t aHf[4][4], aLf[4][4];
        int arw = w * 16 + (lane & 15);
        int acl = ((lane >> 4) & 1) * 8;
#pragma unroll
        for (int s = 0; s < 4; s++) {
            uint32_t off = (uint32_t)((arw * 72 + s * 16 + acl) * 2);
            ldmA(aHf[s], sb + 0 + off);
            ldmA(aLf[s], sb + 18432 + off);
        }
#pragma unroll
        for (int j = 0; j < 16; j++) {
#pragma unroll
            for (int s = 0; s < 4; s++) {
                uint32_t bH[2], bL[2];
                uint32_t off = (uint32_t)(((s * 16 + (lane & 15)) * 136 + j * 8) * 2);
                ldmB(bH, sb + 36864 + off);
                ldmB(bL, sb + 54272 + off);
                mma_bf16(C[j], aHf[s], bH);
                mma_bf16(C[j], aHf[s], bL);
                mma_bf16(C[j], aLf[s], bH);
            }
        }
        __syncthreads();
    }

    int r1 = w * 16 + g;
    const float* bp = bo + ct * 128;
    float* o1 = out + (size_t)(rt * 128 + r1) * DO + ct * 128 + 2 * tg;
    float* o2 = o1 + 8 * DO;
#pragma unroll
    for (int j = 0; j < 16; j++) {
        int cc = j * 8 + 2 * tg;
        *(float2*)(o1 + j * 8) = make_float2(C[j][0] + bp[cc], C[j][1] + bp[cc + 1]);
        *(float2*)(o2 + j * 8) = make_float2(C[j][2] + bp[cc], C[j][3] + bp[cc + 1]);
    }
}

// ==================== launch ====================
extern "C" void kernel_launch(void* const* d_in, const int* in_sizes, int n_in,
                              void* d_out, int out_size) {
    const float* q  = (const float*)d_in[0];
    const float* k  = (const float*)d_in[1];
    const float* v  = (const float*)d_in[2];
    const float* Wq = (const float*)d_in[3];
    const float* bq = (const float*)d_in[4];
    const float* Wk = (const float*)d_in[5];
    const float* bk = (const float*)d_in[6];
    const float* Wv = (const float*)d_in[7];
    const float* bv = (const float*)d_in[8];
    const float* Wo = (const float*)d_in[9];
    const float* bo = (const float*)d_in[10];
    (void)in_sizes; (void)n_in;

    long long osz = (long long)out_size;
    float* attn = nullptr;
    float* out  = nullptr;
    if (osz >= ATTN_ELEMS + OUT_ELEMS) {
        attn = (float*)d_out;
        out  = (float*)d_out + ATTN_ELEMS;
    } else if (osz >= ATTN_ELEMS) {
        attn = (float*)d_out;
    } else {
        out = (float*)d_out;
    }
    if (!attn) cudaGetSymbolAddress((void**)&attn, g_attn_fb);

    float *Qh, *Kh, *Vh;
    cudaGetSymbolAddress((void**)&Qh, g_Qh);
    cudaGetSymbolAddress((void**)&Kh, g_Kh);
    cudaGetSymbolAddress((void**)&Vh, g_Vh);

    cudaFuncSetAttribute(scores_mma_kernel, cudaFuncAttributeMaxDynamicSharedMemorySize, SC_SMEM_BYTES);
    cudaFuncSetAttribute(pv_mma_kernel, cudaFuncAttributeMaxDynamicSharedMemorySize, PV_SMEM_BYTES);
    cudaFuncSetAttribute(oproj_mma_kernel, cudaFuncAttributeMaxDynamicSharedMemorySize, OP_SMEM_BYTES);

    dim3 blk(256);
    proj_kernel<<<dim3(64, 16), blk>>>(q, Wq, bq, Qh);
    proj_kernel<<<dim3(64, 16), blk>>>(k, Wk, bk, Kh);
    proj_kernel<<<dim3(64, 16), blk>>>(v, Wv, bv, Vh);
    scores_mma_kernel<<<dim3(HB, 16), blk, SC_SMEM_BYTES>>>(attn);
    pv_mma_kernel<<<dim3(HB, 16), blk, PV_SMEM_BYTES>>>(attn);
    if (out) oproj_mma_kernel<<<dim3(32, 8), blk, OP_SMEM_BYTES>>>(Wo, bo, out);
}

// round 6
// speedup vs baseline: 2.0182x; 1.2981x over previous
#include <cuda_runtime.h>
#include <cuda_bf16.h>
#include <cstdint>

// Problem constants
#define BATCH  2
#define SEQ    2048
#define DIN    64
#define NHEAD  16
#define DHEAD  64
#define HB     32
#define HD     1024
#define NROWS  4096
#define DO     1024

#define ATTN_ELEMS 134217728LL
#define OUT_ELEMS  4194304LL

// fold 1/sqrt(64) and log2(e): scores kept in log2 domain
#define SCL (0.125f * 1.4426950408889634f)

// -------------------- scratch --------------------
__device__ float g_Qh[HB * SEQ * DHEAD];
__device__ float g_Kh[HB * SEQ * DHEAD];
__device__ float g_Vh[HB * SEQ * DHEAD];
__device__ float g_m[HB * SEQ];
__device__ float g_l[HB * SEQ];
__device__ float g_oh[NROWS * HD];
__device__ float g_attn_fb[134217728];

// -------------------- helpers --------------------
__device__ __forceinline__ uint32_t su32(const void* p) {
    uint32_t a;
    asm("{ .reg .u64 t; cvta.to.shared.u64 t, %1; cvt.u32.u64 %0, t; }" : "=r"(a) : "l"(p));
    return a;
}
__device__ __forceinline__ float ex2f(float x) {
    float y;
    asm("ex2.approx.f32 %0, %1;" : "=f"(y) : "f"(x));
    return y;
}
__device__ __forceinline__ void tf32split(float x, float& h, float& l) {
    asm("cvt.rna.tf32.f32 %0, %1;" : "=f"(h) : "f"(x));
    float r = x - h;
    asm("cvt.rna.tf32.f32 %0, %1;" : "=f"(l) : "f"(r));
}
__device__ __forceinline__ uint32_t pack2bf(float a, float b) {
    __nv_bfloat162 t = __floats2bfloat162_rn(a, b);
    return *(uint32_t*)&t;
}
__device__ __forceinline__ void mma_tf32(float* c, const uint32_t* a, const uint32_t* b) {
    asm volatile("mma.sync.aligned.m16n8k8.row.col.f32.tf32.tf32.f32 "
                 "{%0,%1,%2,%3}, {%4,%5,%6,%7}, {%8,%9}, {%0,%1,%2,%3};"
                 : "+f"(c[0]), "+f"(c[1]), "+f"(c[2]), "+f"(c[3])
                 : "r"(a[0]), "r"(a[1]), "r"(a[2]), "r"(a[3]), "r"(b[0]), "r"(b[1]));
}
__device__ __forceinline__ void mma_bf16(float* c, const uint32_t* a, const uint32_t* b) {
    asm volatile("mma.sync.aligned.m16n8k16.row.col.f32.bf16.bf16.f32 "
                 "{%0,%1,%2,%3}, {%4,%5,%6,%7}, {%8,%9}, {%0,%1,%2,%3};"
                 : "+f"(c[0]), "+f"(c[1]), "+f"(c[2]), "+f"(c[3])
                 : "r"(a[0]), "r"(a[1]), "r"(a[2]), "r"(a[3]), "r"(b[0]), "r"(b[1]));
}
__device__ __forceinline__ void ldmA(uint32_t* r, uint32_t addr) {
    asm volatile("ldmatrix.sync.aligned.m8n8.x4.shared.b16 {%0,%1,%2,%3}, [%4];"
                 : "=r"(r[0]), "=r"(r[1]), "=r"(r[2]), "=r"(r[3]) : "r"(addr));
}
__device__ __forceinline__ void ldmB(uint32_t* r, uint32_t addr) {
    asm volatile("ldmatrix.sync.aligned.m8n8.x2.trans.shared.b16 {%0,%1}, [%2];"
                 : "=r"(r[0]), "=r"(r[1]) : "r"(addr));
}

// ==================== kernel 1: fused QKV projections ====================
__global__ __launch_bounds__(256) void proj_fused_kernel(
    const float* __restrict__ q, const float* __restrict__ k, const float* __restrict__ v,
    const float* __restrict__ Wq, const float* __restrict__ bq,
    const float* __restrict__ Wk, const float* __restrict__ bk,
    const float* __restrict__ Wv, const float* __restrict__ bv,
    float* __restrict__ Qh, float* __restrict__ Kh, float* __restrict__ Vh) {
    __shared__ float Xs[64][65];
    __shared__ float Ws[64][65];
    int rt = blockIdx.x, head = blockIdx.y, z = blockIdx.z, tid = threadIdx.x;
    const float* X = (z == 0) ? q : (z == 1) ? k : v;
    const float* W = (z == 0) ? Wq : (z == 1) ? Wk : Wv;
    const float* bias = (z == 0) ? bq : (z == 1) ? bk : bv;
    float* Out = (z == 0) ? Qh : (z == 1) ? Kh : Vh;

#pragma unroll
    for (int t = 0; t < 4; t++) {
        int f = tid + t * 256;
        int r = f >> 4, c = (f & 15) << 2;
        float4 xv = *(const float4*)(X + (size_t)(rt * 64 + r) * DIN + c);
        Xs[r][c] = xv.x; Xs[r][c + 1] = xv.y; Xs[r][c + 2] = xv.z; Xs[r][c + 3] = xv.w;
        float4 wv = *(const float4*)(W + (size_t)r * HD + head * 64 + c);
        Ws[r][c] = wv.x; Ws[r][c + 1] = wv.y; Ws[r][c + 2] = wv.z; Ws[r][c + 3] = wv.w;
    }
    __syncthreads();
    int ty = tid >> 4, tx = tid & 15;
    int r0 = ty * 4, c0 = tx * 4;
    float acc[4][4] = {};
#pragma unroll
    for (int kk = 0; kk < 64; kk++) {
        float a[4], b[4];
#pragma unroll
        for (int i = 0; i < 4; i++) a[i] = Xs[r0 + i][kk];
#pragma unroll
        for (int j = 0; j < 4; j++) b[j] = Ws[kk][c0 + j];
#pragma unroll
        for (int i = 0; i < 4; i++)
#pragma unroll
            for (int j = 0; j < 4; j++) acc[i][j] = fmaf(a[i], b[j], acc[i][j]);
    }
    int bb = (rt * 64) / SEQ;
    int nbase = rt * 64 - bb * SEQ;
    float bv4[4];
#pragma unroll
    for (int j = 0; j < 4; j++) bv4[j] = bias[head * 64 + c0 + j];
#pragma unroll
    for (int i = 0; i < 4; i++) {
        float4 o;
        o.x = acc[i][0] + bv4[0]; o.y = acc[i][1] + bv4[1];
        o.z = acc[i][2] + bv4[2]; o.w = acc[i][3] + bv4[3];
        size_t row = (size_t)(head * BATCH + bb) * SEQ + nbase + r0 + i;
        *(float4*)(Out + row * DHEAD + c0) = o;
    }
}

// ==================== kernel 2: scores via 3xTF32 mma.sync ====================
// 512 threads, 16 warps; warp = (wr 0..3 rowgroup of 32, wq 0..3 colquad of 32)
// smem floats: Qh[8704] Ql[8704] Kbuf0{h,l} Kbuf1{h,l} stats[1024]
#define SC_BS 8704
#define SC_STAT (6 * SC_BS)
#define SC_SMEM_BYTES ((6 * SC_BS + 1024) * 4)   // 212992

__global__ __launch_bounds__(512, 1) void scores_mma_kernel(float* __restrict__ attn) {
    extern __shared__ float sm[];
    float* Qh_s = sm;
    float* Ql_s = sm + SC_BS;

    int tid = threadIdx.x, lane = tid & 31, w = tid >> 5;
    int g = lane >> 2, tg = lane & 3;
    int wr = w & 3, wq = w >> 2;
    int hb = blockIdx.x, qt = blockIdx.y;
    int r1 = wr * 32 + g;

    // ---- load Q (log2 domain, tf32 split) ----
    const float* Qp = g_Qh + ((size_t)hb * SEQ + qt * 128) * DHEAD;
#pragma unroll
    for (int t = 0; t < 4; t++) {
        int f = tid + t * 512;
        int r = f >> 4, c = (f & 15) << 2;
        float4 v = *(const float4*)(Qp + (size_t)r * DHEAD + c);
        v.x *= SCL; v.y *= SCL; v.z *= SCL; v.w *= SCL;
        float4 h4, l4;
        tf32split(v.x, h4.x, l4.x); tf32split(v.y, h4.y, l4.y);
        tf32split(v.z, h4.z, l4.z); tf32split(v.w, h4.w, l4.w);
        *(float4*)(Qh_s + r * 68 + c) = h4;
        *(float4*)(Ql_s + r * 68 + c) = l4;
    }
    // ---- prologue: K tile 0 -> buf0 ----
    {
        const float* Kp = g_Kh + ((size_t)hb * SEQ) * DHEAD;
        float* Dh = sm + 2 * SC_BS;
        float* Dl = Dh + SC_BS;
#pragma unroll
        for (int t = 0; t < 4; t++) {
            int f = tid + t * 512;
            int r = f >> 4, c = (f & 15) << 2;
            float4 v = *(const float4*)(Kp + (size_t)r * DHEAD + c);
            float4 h4, l4;
            tf32split(v.x, h4.x, l4.x); tf32split(v.y, h4.y, l4.y);
            tf32split(v.z, h4.z, l4.z); tf32split(v.w, h4.w, l4.w);
            *(float4*)(Dh + r * 68 + c) = h4;
            *(float4*)(Dl + r * 68 + c) = l4;
        }
    }
    __syncthreads();

    float mA[2] = {-1e30f, -1e30f}, lA[2] = {0.f, 0.f};
    float mB[2] = {-1e30f, -1e30f}, lB[2] = {0.f, 0.f};
    float* Tbase = attn + (size_t)hb * SEQ * SEQ + (size_t)(qt * 128) * SEQ;

    for (int kt = 0; kt < 16; kt++) {
        float4 pre[4];
        if (kt < 15) {
            const float* Kp = g_Kh + ((size_t)hb * SEQ + (kt + 1) * 128) * DHEAD;
#pragma unroll
            for (int t = 0; t < 4; t++) {
                int f = tid + t * 512;
                int r = f >> 4, c = (f & 15) << 2;
                pre[t] = *(const float4*)(Kp + (size_t)r * DHEAD + c);
            }
        }
        const float* Kh_s = sm + 2 * SC_BS + (kt & 1) * 2 * SC_BS;
        const float* Kl_s = Kh_s + SC_BS;

        float C[2][4][4];
#pragma unroll
        for (int mt = 0; mt < 2; mt++)
#pragma unroll
            for (int j = 0; j < 4; j++) { C[mt][j][0] = C[mt][j][1] = C[mt][j][2] = C[mt][j][3] = 0.f; }

#pragma unroll
        for (int ks = 0; ks < 8; ks++) {
            int c0 = ks * 8 + tg;
            uint32_t aH[2][4], aL[2][4];
#pragma unroll
            for (int mt = 0; mt < 2; mt++) {
                int rr = r1 + mt * 16;
                aH[mt][0] = __float_as_uint(Qh_s[rr * 68 + c0]);
                aH[mt][1] = __float_as_uint(Qh_s[(rr + 8) * 68 + c0]);
                aH[mt][2] = __float_as_uint(Qh_s[rr * 68 + c0 + 4]);
                aH[mt][3] = __float_as_uint(Qh_s[(rr + 8) * 68 + c0 + 4]);
                aL[mt][0] = __float_as_uint(Ql_s[rr * 68 + c0]);
                aL[mt][1] = __float_as_uint(Ql_s[(rr + 8) * 68 + c0]);
                aL[mt][2] = __float_as_uint(Ql_s[rr * 68 + c0 + 4]);
                aL[mt][3] = __float_as_uint(Ql_s[(rr + 8) * 68 + c0 + 4]);
            }
#pragma unroll
            for (int j = 0; j < 4; j++) {
                int kc = wq * 32 + j * 8 + g;
                int kr = ks * 8 + tg;
                uint32_t bH[2], bL[2];
                bH[0] = __float_as_uint(Kh_s[kc * 68 + kr]);
                bH[1] = __float_as_uint(Kh_s[kc * 68 + kr + 4]);
                bL[0] = __float_as_uint(Kl_s[kc * 68 + kr]);
                bL[1] = __float_as_uint(Kl_s[kc * 68 + kr + 4]);
#pragma unroll
                for (int mt = 0; mt < 2; mt++) {
                    mma_tf32(C[mt][j], aH[mt], bH);
                    mma_tf32(C[mt][j], aH[mt], bL);
                    mma_tf32(C[mt][j], aL[mt], bH);
                }
            }
        }

        // online partial stats over this warp's 32 columns
#pragma unroll
        for (int mt = 0; mt < 2; mt++) {
            float mxa = C[mt][0][0], mxb = C[mt][0][2];
#pragma unroll
            for (int j = 0; j < 4; j++) {
                mxa = fmaxf(mxa, fmaxf(C[mt][j][0], C[mt][j][1]));
                mxb = fmaxf(mxb, fmaxf(C[mt][j][2], C[mt][j][3]));
            }
            mxa = fmaxf(mxa, __shfl_xor_sync(0xffffffffu, mxa, 1));
            mxa = fmaxf(mxa, __shfl_xor_sync(0xffffffffu, mxa, 2));
            mxb = fmaxf(mxb, __shfl_xor_sync(0xffffffffu, mxb, 1));
            mxb = fmaxf(mxb, __shfl_xor_sync(0xffffffffu, mxb, 2));
            float M1 = fmaxf(mA[mt], mxa), M2 = fmaxf(mB[mt], mxb);
            float sa = 0.f, sb2 = 0.f;
#pragma unroll
            for (int j = 0; j < 4; j++) {
                sa  += ex2f(C[mt][j][0] - M1) + ex2f(C[mt][j][1] - M1);
                sb2 += ex2f(C[mt][j][2] - M2) + ex2f(C[mt][j][3] - M2);
            }
            sa  += __shfl_xor_sync(0xffffffffu, sa, 1);
            sa  += __shfl_xor_sync(0xffffffffu, sa, 2);
            sb2 += __shfl_xor_sync(0xffffffffu, sb2, 1);
            sb2 += __shfl_xor_sync(0xffffffffu, sb2, 2);
            lA[mt] = lA[mt] * ex2f(mA[mt] - M1) + sa;  mA[mt] = M1;
            lB[mt] = lB[mt] * ex2f(mB[mt] - M2) + sb2; mB[mt] = M2;
        }

        // store raw log2-domain scores
#pragma unroll
        for (int mt = 0; mt < 2; mt++) {
            int rr = r1 + mt * 16;
            float* p1 = Tbase + (size_t)rr * SEQ + kt * 128 + wq * 32 + 2 * tg;
            float* p2 = p1 + (size_t)8 * SEQ;
#pragma unroll
            for (int j = 0; j < 4; j++) {
                *(float2*)(p1 + j * 8) = make_float2(C[mt][j][0], C[mt][j][1]);
                *(float2*)(p2 + j * 8) = make_float2(C[mt][j][2], C[mt][j][3]);
            }
        }

        if (kt < 15) {
            float* Dh = sm + 2 * SC_BS + ((kt + 1) & 1) * 2 * SC_BS;
            float* Dl = Dh + SC_BS;
#pragma unroll
            for (int t = 0; t < 4; t++) {
                int f = tid + t * 512;
                int r = f >> 4, c = (f & 15) << 2;
                float4 v = pre[t];
                float4 h4, l4;
                tf32split(v.x, h4.x, l4.x); tf32split(v.y, h4.y, l4.y);
                tf32split(v.z, h4.z, l4.z); tf32split(v.w, h4.w, l4.w);
                *(float4*)(Dh + r * 68 + c) = h4;
                *(float4*)(Dl + r * 68 + c) = l4;
            }
        }
        __syncthreads();
    }

    // combine 4 column-quad partials per row
    float* smm = sm + SC_STAT;
    float* sml = smm + 512;
    if (tg == 0) {
#pragma unroll
        for (int mt = 0; mt < 2; mt++) {
            int rr = r1 + mt * 16;
            smm[wq * 128 + rr] = mA[mt];      sml[wq * 128 + rr] = lA[mt];
            smm[wq * 128 + rr + 8] = mB[mt];  sml[wq * 128 + rr + 8] = lB[mt];
        }
    }
    __syncthreads();
    if (tid < 128) {
        float M = smm[tid];
#pragma unroll
        for (int qd = 1; qd < 4; qd++) M = fmaxf(M, smm[qd * 128 + tid]);
        float L = 0.f;
#pragma unroll
        for (int qd = 0; qd < 4; qd++) L += sml[qd * 128 + tid] * ex2f(smm[qd * 128 + tid] - M);
        int base = hb * SEQ + qt * 128;
        g_m[base + tid] = M;
        g_l[base + tid] = L;
    }
}

// ==================== kernel 3: normalize + PV via bf16-3x mma.sync ====================
// 512 threads; double-buffered smem; warp = (wr 0..7 rows of 16, wc 0..1 col half of 32)
#define PV_PBUF 55296
#define PV_STAT 110592
#define PV_SMEM_BYTES 111616

__global__ __launch_bounds__(512, 1) void pv_mma_kernel(float* __restrict__ attn) {
    extern __shared__ char smc[];
    uint32_t sb = su32(smc);
    float* msm  = (float*)(smc + PV_STAT);
    float* ilsm = (float*)(smc + PV_STAT + 512);

    int tid = threadIdx.x, lane = tid & 31, w = tid >> 5;
    int g = lane >> 2, tg = lane & 3;
    int wr = w & 7, wc = w >> 3;
    int hb = blockIdx.x, qt = blockIdx.y;

    if (tid < 128) {
        msm[tid] = g_m[hb * SEQ + qt * 128 + tid];
        ilsm[tid] = 1.0f / g_l[hb * SEQ + qt * 128 + tid];
    }
    __syncthreads();

    float* arow = attn + (size_t)hb * SEQ * SEQ + (size_t)(qt * 128) * SEQ;
    float C[4][4];
#pragma unroll
    for (int j = 0; j < 4; j++) { C[j][0] = C[j][1] = C[j][2] = C[j][3] = 0.f; }

    float4 aR[4], vR[2];
    // prologue: load + process chunk 0 into buf 0
    {
        const float* Vp = g_Vh + ((size_t)hb * SEQ) * DHEAD;
#pragma unroll
        for (int t = 0; t < 4; t++) {
            int f = tid + t * 512;
            int r = f >> 4, c = (f & 15) << 2;
            aR[t] = *(const float4*)(arow + (size_t)r * SEQ + c);
        }
#pragma unroll
        for (int t = 0; t < 2; t++) {
            int f = tid + t * 512;
            int kk = f >> 4, dd = (f & 15) << 2;
            vR[t] = *(const float4*)(Vp + (size_t)kk * DHEAD + dd);
        }
        char* bufc = smc;
#pragma unroll
        for (int t = 0; t < 4; t++) {
            int f = tid + t * 512;
            int r = f >> 4, c = (f & 15) << 2;
            float4 v = aR[t];
            float mm = msm[r], il = ilsm[r];
            v.x = ex2f(v.x - mm) * il; v.y = ex2f(v.y - mm) * il;
            v.z = ex2f(v.z - mm) * il; v.w = ex2f(v.w - mm) * il;
            *(float4*)(arow + (size_t)r * SEQ + c) = v;
            float hx = __bfloat162float(__float2bfloat16_rn(v.x));
            float hy = __bfloat162float(__float2bfloat16_rn(v.y));
            float hz = __bfloat162float(__float2bfloat16_rn(v.z));
            float hw = __bfloat162float(__float2bfloat16_rn(v.w));
            uint2 hp, lp;
            hp.x = pack2bf(hx, hy); hp.y = pack2bf(hz, hw);
            lp.x = pack2bf(v.x - hx, v.y - hy); lp.y = pack2bf(v.z - hz, v.w - hw);
            *(uint2*)(bufc + (r * 72 + c) * 2) = hp;
            *(uint2*)(bufc + 18432 + (r * 72 + c) * 2) = lp;
        }
#pragma unroll
        for (int t = 0; t < 2; t++) {
            int f = tid + t * 512;
            int kk = f >> 4, dd = (f & 15) << 2;
            float4 v = vR[t];
            float hx = __bfloat162float(__float2bfloat16_rn(v.x));
            float hy = __bfloat162float(__float2bfloat16_rn(v.y));
            float hz = __bfloat162float(__float2bfloat16_rn(v.z));
            float hw = __bfloat162float(__float2bfloat16_rn(v.w));
            uint2 hp, lp;
            hp.x = pack2bf(hx, hy); hp.y = pack2bf(hz, hw);
            lp.x = pack2bf(v.x - hx, v.y - hy); lp.y = pack2bf(v.z - hz, v.w - hw);
            *(uint2*)(bufc + 36864 + (kk * 72 + dd) * 2) = hp;
            *(uint2*)(bufc + 46080 + (kk * 72 + dd) * 2) = lp;
        }
    }
    __syncthreads();

    int arw = wr * 16 + (lane & 15);
    int acl = ((lane >> 4) & 1) * 8;

    for (int kc = 0; kc < 32; kc++) {
        int b = kc & 1;
        if (kc < 31) {
            const float* Vp = g_Vh + ((size_t)hb * SEQ + (kc + 1) * 64) * DHEAD;
#pragma unroll
            for (int t = 0; t < 4; t++) {
                int f = tid + t * 512;
                int r = f >> 4, c = (f & 15) << 2;
                aR[t] = *(const float4*)(arow + (size_t)r * SEQ + (kc + 1) * 64 + c);
            }
#pragma unroll
            for (int t = 0; t < 2; t++) {
                int f = tid + t * 512;
                int kk = f >> 4, dd = (f & 15) << 2;
                vR[t] = *(const float4*)(Vp + (size_t)kk * DHEAD + dd);
            }
        }
        // mma from buffer b
        uint32_t bufb = sb + b * PV_PBUF;
        uint32_t aHf[4][4], aLf[4][4];
#pragma unroll
        for (int s = 0; s < 4; s++) {
            uint32_t off = (uint32_t)((arw * 72 + s * 16 + acl) * 2);
            ldmA(aHf[s], bufb + off);
            ldmA(aLf[s], bufb + 18432 + off);
        }
#pragma unroll
        for (int j = 0; j < 4; j++) {
#pragma unroll
            for (int s = 0; s < 4; s++) {
                uint32_t bH[2], bL[2];
                uint32_t off = (uint32_t)(((s * 16 + (lane & 15)) * 72 + wc * 32 + j * 8) * 2);
                ldmB(bH, bufb + 36864 + off);
                ldmB(bL, bufb + 46080 + off);
                mma_bf16(C[j], aHf[s], bH);
                mma_bf16(C[j], aHf[s], bL);
                mma_bf16(C[j], aLf[s], bH);
            }
        }
        if (kc < 31) {
            char* bufc = smc + (b ^ 1) * PV_PBUF;
#pragma unroll
            for (int t = 0; t < 4; t++) {
                int f = tid + t * 512;
                int r = f >> 4, c = (f & 15) << 2;
                float4 v = aR[t];
                float mm = msm[r], il = ilsm[r];
                v.x = ex2f(v.x - mm) * il; v.y = ex2f(v.y - mm) * il;
                v.z = ex2f(v.z - mm) * il; v.w = ex2f(v.w - mm) * il;
                *(float4*)(arow + (size_t)r * SEQ + (kc + 1) * 64 + c) = v;
                float hx = __bfloat162float(__float2bfloat16_rn(v.x));
                float hy = __bfloat162float(__float2bfloat16_rn(v.y));
                float hz = __bfloat162float(__float2bfloat16_rn(v.z));
                float hw = __bfloat162float(__float2bfloat16_rn(v.w));
                uint2 hp, lp;
                hp.x = pack2bf(hx, hy); hp.y = pack2bf(hz, hw);
                lp.x = pack2bf(v.x - hx, v.y - hy); lp.y = pack2bf(v.z - hz, v.w - hw);
                *(uint2*)(bufc + (r * 72 + c) * 2) = hp;
                *(uint2*)(bufc + 18432 + (r * 72 + c) * 2) = lp;
            }
#pragma unroll
            for (int t = 0; t < 2; t++) {
                int f = tid + t * 512;
                int kk = f >> 4, dd = (f & 15) << 2;
                float4 v = vR[t];
                float hx = __bfloat162float(__float2bfloat16_rn(v.x));
                float hy = __bfloat162float(__float2bfloat16_rn(v.y));
                float hz = __bfloat162float(__float2bfloat16_rn(v.z));
                float hw = __bfloat162float(__float2bfloat16_rn(v.w));
                uint2 hp, lp;
                hp.x = pack2bf(hx, hy); hp.y = pack2bf(hz, hw);
                lp.x = pack2bf(v.x - hx, v.y - hy); lp.y = pack2bf(v.z - hz, v.w - hw);
                *(uint2*)(bufc + 36864 + (kk * 72 + dd) * 2) = hp;
                *(uint2*)(bufc + 46080 + (kk * 72 + dd) * 2) = lp;
            }
        }
        __syncthreads();
    }

    int h = hb >> 1, bb = hb & 1;
    int r1 = wr * 16 + g;
    float* o1 = g_oh + ((size_t)(bb * SEQ + qt * 128 + r1)) * HD + h * 64 + wc * 32 + 2 * tg;
    float* o2 = o1 + 8 * HD;
#pragma unroll
    for (int j = 0; j < 4; j++) {
        *(float2*)(o1 + j * 8) = make_float2(C[j][0], C[j][1]);
        *(float2*)(o2 + j * 8) = make_float2(C[j][2], C[j][3]);
    }
}

// ==================== kernel 4: out projection via bf16-3x mma.sync ====================
// 512 threads; double-buffered; warp = (wr 0..7 rows of 16, wc 0..1 col half of 64)
#define OP_PBUF 71680
#define OP_SMEM_BYTES 143360

__global__ __launch_bounds__(512, 1) void oproj_mma_kernel(
    const float* __restrict__ Wo, const float* __restrict__ bo, float* __restrict__ out) {
    extern __shared__ char smc[];
    uint32_t sb = su32(smc);

    int tid = threadIdx.x, lane = tid & 31, w = tid >> 5;
    int g = lane >> 2, tg = lane & 3;
    int wr = w & 7, wc = w >> 3;
    int rt = blockIdx.x, ct = blockIdx.y;

    float C[8][4];
#pragma unroll
    for (int j = 0; j < 8; j++) { C[j][0] = C[j][1] = C[j][2] = C[j][3] = 0.f; }

    float4 aR[4], bR[4];
    // prologue
    {
#pragma unroll
        for (int t = 0; t < 4; t++) {
            int f = tid + t * 512;
            int r = f >> 4, c = (f & 15) << 2;
            aR[t] = *(const float4*)(g_oh + (size_t)(rt * 128 + r) * HD + c);
        }
#pragma unroll
        for (int t = 0; t < 4; t++) {
            int f = tid + t * 512;
            int kk = f >> 5, nn = (f & 31) << 2;
            bR[t] = *(const float4*)(Wo + (size_t)kk * DO + ct * 128 + nn);
        }
        char* bufc = smc;
#pragma unroll
        for (int t = 0; t < 4; t++) {
            int f = tid + t * 512;
            int r = f >> 4, c = (f & 15) << 2;
            float4 v = aR[t];
            float hx = __bfloat162float(__float2bfloat16_rn(v.x));
            float hy = __bfloat162float(__float2bfloat16_rn(v.y));
            float hz = __bfloat162float(__float2bfloat16_rn(v.z));
            float hw = __bfloat162float(__float2bfloat16_rn(v.w));
            uint2 hp, lp;
            hp.x = pack2bf(hx, hy); hp.y = pack2bf(hz, hw);
            lp.x = pack2bf(v.x - hx, v.y - hy); lp.y = pack2bf(v.z - hz, v.w - hw);
            *(uint2*)(bufc + (r * 72 + c) * 2) = hp;
            *(uint2*)(bufc + 18432 + (r * 72 + c) * 2) = lp;
        }
#pragma unroll
        for (int t = 0; t < 4; t++) {
            int f = tid + t * 512;
            int kk = f >> 5, nn = (f & 31) << 2;
            float4 v = bR[t];
            float hx = __bfloat162float(__float2bfloat16_rn(v.x));
            float hy = __bfloat162float(__float2bfloat16_rn(v.y));
            float hz = __bfloat162float(__float2bfloat16_rn(v.z));
            float hw = __bfloat162float(__float2bfloat16_rn(v.w));
            uint2 hp, lp;
            hp.x = pack2bf(hx, hy); hp.y = pack2bf(hz, hw);
            lp.x = pack2bf(v.x - hx, v.y - hy); lp.y = pack2bf(v.z - hz, v.w - hw);
            *(uint2*)(bufc + 36864 + (kk * 136 + nn) * 2) = hp;
            *(uint2*)(bufc + 54272 + (kk * 136 + nn) * 2) = lp;
        }
    }
    __syncthreads();

    int arw = wr * 16 + (lane & 15);
    int acl = ((lane >> 4) & 1) * 8;

    for (int kc = 0; kc < 16; kc++) {
        int b = kc & 1;
        if (kc < 15) {
#pragma unroll
            for (int t = 0; t < 4; t++) {
                int f = tid + t * 512;
                int r = f >> 4, c = (f & 15) << 2;
                aR[t] = *(const float4*)(g_oh + (size_t)(rt * 128 + r) * HD + (kc + 1) * 64 + c);
            }
#pragma unroll
            for (int t = 0; t < 4; t++) {
                int f = tid + t * 512;
                int kk = f >> 5, nn = (f & 31) << 2;
                bR[t] = *(const float4*)(Wo + (size_t)((kc + 1) * 64 + kk) * DO + ct * 128 + nn);
            }
        }
        uint32_t bufb = sb + b * OP_PBUF;
        uint32_t aHf[4][4], aLf[4][4];
#pragma unroll
        for (int s = 0; s < 4; s++) {
            uint32_t off = (uint32_t)((arw * 72 + s * 16 + acl) * 2);
            ldmA(aHf[s], bufb + off);
            ldmA(aLf[s], bufb + 18432 + off);
        }
#pragma unroll
        for (int j = 0; j < 8; j++) {
#pragma unroll
            for (int s = 0; s < 4; s++) {
                uint32_t bH[2], bL[2];
                uint32_t off = (uint32_t)(((s * 16 + (lane & 15)) * 136 + wc * 64 + j * 8) * 2);
                ldmB(bH, bufb + 36864 + off);
                ldmB(bL, bufb + 54272 + off);
                mma_bf16(C[j], aHf[s], bH);
                mma_bf16(C[j], aHf[s], bL);
                mma_bf16(C[j], aLf[s], bH);
            }
        }
        if (kc < 15) {
            char* bufc = smc + (b ^ 1) * OP_PBUF;
#pragma unroll
            for (int t = 0; t < 4; t++) {
                int f = tid + t * 512;
                int r = f >> 4, c = (f & 15) << 2;
                float4 v = aR[t];
                float hx = __bfloat162float(__float2bfloat16_rn(v.x));
                float hy = __bfloat162float(__float2bfloat16_rn(v.y));
                float hz = __bfloat162float(__float2bfloat16_rn(v.z));
                float hw = __bfloat162float(__float2bfloat16_rn(v.w));
                uint2 hp, lp;
                hp.x = pack2bf(hx, hy); hp.y = pack2bf(hz, hw);
                lp.x = pack2bf(v.x - hx, v.y - hy); lp.y = pack2bf(v.z - hz, v.w - hw);
                *(uint2*)(bufc + (r * 72 + c) * 2) = hp;
                *(uint2*)(bufc + 18432 + (r * 72 + c) * 2) = lp;
            }
#pragma unroll
            for (int t = 0; t < 4; t++) {
                int f = tid + t * 512;
                int kk = f >> 5, nn = (f & 31) << 2;
                float4 v = bR[t];
                float hx = __bfloat162float(__float2bfloat16_rn(v.x));
                float hy = __bfloat162float(__float2bfloat16_rn(v.y));
                float hz = __bfloat162float(__float2bfloat16_rn(v.z));
                float hw = __bfloat162float(__float2bfloat16_rn(v.w));
                uint2 hp, lp;
                hp.x = pack2bf(hx, hy); hp.y = pack2bf(hz, hw);
                lp.x = pack2bf(v.x - hx, v.y - hy); lp.y = pack2bf(v.z - hz, v.w - hw);
                *(uint2*)(bufc + 36864 + (kk * 136 + nn) * 2) = hp;
                *(uint2*)(bufc + 54272 + (kk * 136 + nn) * 2) = lp;
            }
        }
        __syncthreads();
    }

    int r1 = wr * 16 + g;
    const float* bp = bo + ct * 128 + wc * 64;
    float* o1 = out + (size_t)(rt * 128 + r1) * DO + ct * 128 + wc * 64 + 2 * tg;
    float* o2 = o1 + 8 * DO;
#pragma unroll
    for (int j = 0; j < 8; j++) {
        int cc = j * 8 + 2 * tg;
        *(float2*)(o1 + j * 8) = make_float2(C[j][0] + bp[cc], C[j][1] + bp[cc + 1]);
        *(float2*)(o2 + j * 8) = make_float2(C[j][2] + bp[cc], C[j][3] + bp[cc + 1]);
    }
}

// ==================== launch ====================
extern "C" void kernel_launch(void* const* d_in, const int* in_sizes, int n_in,
                              void* d_out, int out_size) {
    const float* q  = (const float*)d_in[0];
    const float* k  = (const float*)d_in[1];
    const float* v  = (const float*)d_in[2];
    const float* Wq = (const float*)d_in[3];
    const float* bq = (const float*)d_in[4];
    const float* Wk = (const float*)d_in[5];
    const float* bk = (const float*)d_in[6];
    const float* Wv = (const float*)d_in[7];
    const float* bv = (const float*)d_in[8];
    const float* Wo = (const float*)d_in[9];
    const float* bo = (const float*)d_in[10];
    (void)in_sizes; (void)n_in;

    long long osz = (long long)out_size;
    float* attn = nullptr;
    float* out  = nullptr;
    if (osz >= ATTN_ELEMS + OUT_ELEMS) {
        attn = (float*)d_out;
        out  = (float*)d_out + ATTN_ELEMS;
    } else if (osz >= ATTN_ELEMS) {
        attn = (float*)d_out;
    } else {
        out = (float*)d_out;
    }
    if (!attn) cudaGetSymbolAddress((void**)&attn, g_attn_fb);

    float *Qh, *Kh, *Vh;
    cudaGetSymbolAddress((void**)&Qh, g_Qh);
    cudaGetSymbolAddress((void**)&Kh, g_Kh);
    cudaGetSymbolAddress((void**)&Vh, g_Vh);

    cudaFuncSetAttribute(scores_mma_kernel, cudaFuncAttributeMaxDynamicSharedMemorySize, SC_SMEM_BYTES);
    cudaFuncSetAttribute(pv_mma_kernel, cudaFuncAttributeMaxDynamicSharedMemorySize, PV_SMEM_BYTES);
    cudaFuncSetAttribute(oproj_mma_kernel, cudaFuncAttributeMaxDynamicSharedMemorySize, OP_SMEM_BYTES);

    proj_fused_kernel<<<dim3(64, 16, 3), 256>>>(q, k, v, Wq, bq, Wk, bk, Wv, bv, Qh, Kh, Vh);
    scores_mma_kernel<<<dim3(HB, 16), 512, SC_SMEM_BYTES>>>(attn);
    pv_mma_kernel<<<dim3(HB, 16), 512, PV_SMEM_BYTES>>>(attn);
    if (out) oproj_mma_kernel<<<dim3(32, 8), 512, OP_SMEM_BYTES>>>(Wo, bo, out);
}

// round 10
// speedup vs baseline: 2.5432x; 1.2601x over previous
#include <cuda_runtime.h>
#include <cuda_fp16.h>
#include <cstdint>

// Problem constants
#define BATCH  2
#define SEQ    2048
#define DIN    64
#define NHEAD  16
#define DHEAD  64
#define HB     32
#define HD     1024
#define NROWS  4096
#define DO     1024

#define ATTN_ELEMS 134217728LL
#define OUT_ELEMS  4194304LL

// fold 1/sqrt(64) and log2(e): scores kept in log2 domain
#define SCL (0.125f * 1.4426950408889634f)

// -------------------- scratch --------------------
__device__ float g_Qh[HB * SEQ * DHEAD];
__device__ float g_Kh[HB * SEQ * DHEAD];
__device__ float g_Vh[HB * SEQ * DHEAD];
__device__ float g_m[HB * SEQ];
__device__ float g_l[HB * SEQ];
__device__ float g_oh[NROWS * HD];
__device__ float g_attn_fb[134217728];

// -------------------- helpers --------------------
__device__ __forceinline__ uint32_t su32(const void* p) {
    uint32_t a;
    asm("{ .reg .u64 t; cvta.to.shared.u64 t, %1; cvt.u32.u64 %0, t; }" : "=r"(a) : "l"(p));
    return a;
}
__device__ __forceinline__ float ex2f(float x) {
    float y;
    asm("ex2.approx.f32 %0, %1;" : "=f"(y) : "f"(x));
    return y;
}
// f32 -> f16 hi/lo split of a float4: hp = hi halves, lp = lo halves
__device__ __forceinline__ void h2split(float4 v, uint2& hp, uint2& lp) {
    __half2 h0 = __floats2half2_rn(v.x, v.y);
    __half2 h1 = __floats2half2_rn(v.z, v.w);
    float2 f0 = __half22float2(h0), f1 = __half22float2(h1);
    __half2 l0 = __floats2half2_rn(v.x - f0.x, v.y - f0.y);
    __half2 l1 = __floats2half2_rn(v.z - f1.x, v.w - f1.y);
    hp.x = *(uint32_t*)&h0; hp.y = *(uint32_t*)&h1;
    lp.x = *(uint32_t*)&l0; lp.y = *(uint32_t*)&l1;
}
__device__ __forceinline__ void mma_f16(float* c, const uint32_t* a, const uint32_t* b) {
    asm volatile("mma.sync.aligned.m16n8k16.row.col.f32.f16.f16.f32 "
                 "{%0,%1,%2,%3}, {%4,%5,%6,%7}, {%8,%9}, {%0,%1,%2,%3};"
                 : "+f"(c[0]), "+f"(c[1]), "+f"(c[2]), "+f"(c[3])
                 : "r"(a[0]), "r"(a[1]), "r"(a[2]), "r"(a[3]), "r"(b[0]), "r"(b[1]));
}
__device__ __forceinline__ void ldmA(uint32_t* r, uint32_t addr) {
    asm volatile("ldmatrix.sync.aligned.m8n8.x4.shared.b16 {%0,%1,%2,%3}, [%4];"
                 : "=r"(r[0]), "=r"(r[1]), "=r"(r[2]), "=r"(r[3]) : "r"(addr));
}
__device__ __forceinline__ void ldmB(uint32_t* r, uint32_t addr) {  // trans (B with k contiguous in rows)
    asm volatile("ldmatrix.sync.aligned.m8n8.x2.trans.shared.b16 {%0,%1}, [%2];"
                 : "=r"(r[0]), "=r"(r[1]) : "r"(addr));
}
__device__ __forceinline__ void ldmBn(uint32_t* r, uint32_t addr) { // non-trans (B rows = n, cols = k)
    asm volatile("ldmatrix.sync.aligned.m8n8.x2.shared.b16 {%0,%1}, [%2];"
                 : "=r"(r[0]), "=r"(r[1]) : "r"(addr));
}

// ==================== kernel 1: fused QKV projections ====================
__global__ __launch_bounds__(256) void proj_fused_kernel(
    const float* __restrict__ q, const float* __restrict__ k, const float* __restrict__ v,
    const float* __restrict__ Wq, const float* __restrict__ bq,
    const float* __restrict__ Wk, const float* __restrict__ bk,
    const float* __restrict__ Wv, const float* __restrict__ bv,
    float* __restrict__ Qh, float* __restrict__ Kh, float* __restrict__ Vh) {
    __shared__ float Xs[64][65];
    __shared__ float Ws[64][65];
    int rt = blockIdx.x, head = blockIdx.y, z = blockIdx.z, tid = threadIdx.x;
    const float* X = (z == 0) ? q : (z == 1) ? k : v;
    const float* W = (z == 0) ? Wq : (z == 1) ? Wk : Wv;
    const float* bias = (z == 0) ? bq : (z == 1) ? bk : bv;
    float* Out = (z == 0) ? Qh : (z == 1) ? Kh : Vh;

#pragma unroll
    for (int t = 0; t < 4; t++) {
        int f = tid + t * 256;
        int r = f >> 4, c = (f & 15) << 2;
        float4 xv = *(const float4*)(X + (size_t)(rt * 64 + r) * DIN + c);
        Xs[r][c] = xv.x; Xs[r][c + 1] = xv.y; Xs[r][c + 2] = xv.z; Xs[r][c + 3] = xv.w;
        float4 wv = *(const float4*)(W + (size_t)r * HD + head * 64 + c);
        Ws[r][c] = wv.x; Ws[r][c + 1] = wv.y; Ws[r][c + 2] = wv.z; Ws[r][c + 3] = wv.w;
    }
    __syncthreads();
    int ty = tid >> 4, tx = tid & 15;
    int r0 = ty * 4, c0 = tx * 4;
    float acc[4][4] = {};
#pragma unroll
    for (int kk = 0; kk < 64; kk++) {
        float a[4], b[4];
#pragma unroll
        for (int i = 0; i < 4; i++) a[i] = Xs[r0 + i][kk];
#pragma unroll
        for (int j = 0; j < 4; j++) b[j] = Ws[kk][c0 + j];
#pragma unroll
        for (int i = 0; i < 4; i++)
#pragma unroll
            for (int j = 0; j < 4; j++) acc[i][j] = fmaf(a[i], b[j], acc[i][j]);
    }
    int bb = (rt * 64) / SEQ;
    int nbase = rt * 64 - bb * SEQ;
    float bv4[4];
#pragma unroll
    for (int j = 0; j < 4; j++) bv4[j] = bias[head * 64 + c0 + j];
#pragma unroll
    for (int i = 0; i < 4; i++) {
        float4 o;
        o.x = acc[i][0] + bv4[0]; o.y = acc[i][1] + bv4[1];
        o.z = acc[i][2] + bv4[2]; o.w = acc[i][3] + bv4[3];
        size_t row = (size_t)(head * BATCH + bb) * SEQ + nbase + r0 + i;
        *(float4*)(Out + row * DHEAD + c0) = o;
    }
}

// ==================== kernel 2: scores via f16-3x m16n8k16 ====================
// 512 threads, 16 warps; warp = (wr 0..3 rowgroup of 32, wq 0..3 colquad of 32)
// smem bytes: QH 0 (18432), QL 18432, Kbuf{0,1}: H/L 18432 each, stats at 110592
#define SC_QH 0
#define SC_QL 18432
#define SC_KB0 36864
#define SC_KBSTRIDE 36864
#define SC_STATS 110592
#define SC_SMEM_BYTES 114688

__global__ __launch_bounds__(512, 1) void scores_mma_kernel(float* __restrict__ attn) {
    extern __shared__ char smc[];
    uint32_t sb = su32(smc);

    int tid = threadIdx.x, lane = tid & 31, w = tid >> 5;
    int g = lane >> 2, tg = lane & 3;
    int wr = w & 3, wq = w >> 2;
    int hb = blockIdx.x, qt = blockIdx.y;
    int r1 = wr * 32 + g;

    // ---- load Q (log2 domain, f16 hi/lo split), row-major [row][dim] stride 72 halves ----
    const float* Qp = g_Qh + ((size_t)hb * SEQ + qt * 128) * DHEAD;
#pragma unroll
    for (int t = 0; t < 4; t++) {
        int f = tid + t * 512;
        int r = f >> 4, c = (f & 15) << 2;
        float4 v = *(const float4*)(Qp + (size_t)r * DHEAD + c);
        v.x *= SCL; v.y *= SCL; v.z *= SCL; v.w *= SCL;
        uint2 hp, lp;
        h2split(v, hp, lp);
        *(uint2*)(smc + SC_QH + (r * 72 + c) * 2) = hp;
        *(uint2*)(smc + SC_QL + (r * 72 + c) * 2) = lp;
    }
    // ---- prologue: K tile 0 -> buf0, row-major [key][dim] stride 72 ----
    {
        const float* Kp = g_Kh + ((size_t)hb * SEQ) * DHEAD;
#pragma unroll
        for (int t = 0; t < 4; t++) {
            int f = tid + t * 512;
            int r = f >> 4, c = (f & 15) << 2;
            float4 v = *(const float4*)(Kp + (size_t)r * DHEAD + c);
            uint2 hp, lp;
            h2split(v, hp, lp);
            *(uint2*)(smc + SC_KB0 + (r * 72 + c) * 2) = hp;
            *(uint2*)(smc + SC_KB0 + 18432 + (r * 72 + c) * 2) = lp;
        }
    }
    __syncthreads();

    float mA[2] = {-1e30f, -1e30f}, lA[2] = {0.f, 0.f};
    float mB[2] = {-1e30f, -1e30f}, lB[2] = {0.f, 0.f};
    float* Tbase = attn + (size_t)hb * SEQ * SEQ + (size_t)(qt * 128) * SEQ;

    // fragment addressing constants
    int arow = (lane & 15);                 // row within 16-row A block
    int acl = ((lane >> 4) & 1) * 8;        // 8-col half select for ldmatrix x4
    int bkey = wq * 32 + (lane & 7);        // key row for non-trans B ldmatrix
    int bch = ((lane >> 3) & 1) * 8;        // dim chunk within k16

    for (int kt = 0; kt < 16; kt++) {
        float4 pre[4];
        if (kt < 15) {
            const float* Kp = g_Kh + ((size_t)hb * SEQ + (kt + 1) * 128) * DHEAD;
#pragma unroll
            for (int t = 0; t < 4; t++) {
                int f = tid + t * 512;
                int r = f >> 4, c = (f & 15) << 2;
                pre[t] = *(const float4*)(Kp + (size_t)r * DHEAD + c);
            }
        }
        uint32_t kbH = sb + SC_KB0 + (kt & 1) * SC_KBSTRIDE;
        uint32_t kbL = kbH + 18432;

        float C[2][4][4];
#pragma unroll
        for (int mt = 0; mt < 2; mt++)
#pragma unroll
            for (int j = 0; j < 4; j++) { C[mt][j][0] = C[mt][j][1] = C[mt][j][2] = C[mt][j][3] = 0.f; }

#pragma unroll
        for (int ks = 0; ks < 4; ks++) {
            uint32_t aH[2][4], aL[2][4];
#pragma unroll
            for (int mt = 0; mt < 2; mt++) {
                uint32_t off = (uint32_t)(((wr * 32 + mt * 16 + arow) * 72 + ks * 16 + acl) * 2);
                ldmA(aH[mt], sb + SC_QH + off);
                ldmA(aL[mt], sb + SC_QL + off);
            }
#pragma unroll
            for (int j = 0; j < 4; j++) {
                uint32_t boff = (uint32_t)(((bkey + j * 8) * 72 + ks * 16 + bch) * 2);
                uint32_t bH[2], bL[2];
                ldmBn(bH, kbH + boff);
                ldmBn(bL, kbL + boff);
#pragma unroll
                for (int mt = 0; mt < 2; mt++) {
                    mma_f16(C[mt][j], aH[mt], bH);
                    mma_f16(C[mt][j], aH[mt], bL);
                    mma_f16(C[mt][j], aL[mt], bH);
                }
            }
        }

        // online partial stats over this warp's 32 columns
#pragma unroll
        for (int mt = 0; mt < 2; mt++) {
            float mxa = C[mt][0][0], mxb = C[mt][0][2];
#pragma unroll
            for (int j = 0; j < 4; j++) {
                mxa = fmaxf(mxa, fmaxf(C[mt][j][0], C[mt][j][1]));
                mxb = fmaxf(mxb, fmaxf(C[mt][j][2], C[mt][j][3]));
            }
            mxa = fmaxf(mxa, __shfl_xor_sync(0xffffffffu, mxa, 1));
            mxa = fmaxf(mxa, __shfl_xor_sync(0xffffffffu, mxa, 2));
            mxb = fmaxf(mxb, __shfl_xor_sync(0xffffffffu, mxb, 1));
            mxb = fmaxf(mxb, __shfl_xor_sync(0xffffffffu, mxb, 2));
            float M1 = fmaxf(mA[mt], mxa), M2 = fmaxf(mB[mt], mxb);
            float sa = 0.f, sb2 = 0.f;
#pragma unroll
            for (int j = 0; j < 4; j++) {
                sa  += ex2f(C[mt][j][0] - M1) + ex2f(C[mt][j][1] - M1);
                sb2 += ex2f(C[mt][j][2] - M2) + ex2f(C[mt][j][3] - M2);
            }
            sa  += __shfl_xor_sync(0xffffffffu, sa, 1);
            sa  += __shfl_xor_sync(0xffffffffu, sa, 2);
            sb2 += __shfl_xor_sync(0xffffffffu, sb2, 1);
            sb2 += __shfl_xor_sync(0xffffffffu, sb2, 2);
            lA[mt] = lA[mt] * ex2f(mA[mt] - M1) + sa;  mA[mt] = M1;
            lB[mt] = lB[mt] * ex2f(mB[mt] - M2) + sb2; mB[mt] = M2;
        }

        // store raw log2-domain scores
#pragma unroll
        for (int mt = 0; mt < 2; mt++) {
            int rr = r1 + mt * 16;
            float* p1 = Tbase + (size_t)rr * SEQ + kt * 128 + wq * 32 + 2 * tg;
            float* p2 = p1 + (size_t)8 * SEQ;
#pragma unroll
            for (int j = 0; j < 4; j++) {
                *(float2*)(p1 + j * 8) = make_float2(C[mt][j][0], C[mt][j][1]);
                *(float2*)(p2 + j * 8) = make_float2(C[mt][j][2], C[mt][j][3]);
            }
        }

        if (kt < 15) {
            char* kb = smc + SC_KB0 + ((kt + 1) & 1) * SC_KBSTRIDE;
#pragma unroll
            for (int t = 0; t < 4; t++) {
                int f = tid + t * 512;
                int r = f >> 4, c = (f & 15) << 2;
                uint2 hp, lp;
                h2split(pre[t], hp, lp);
                *(uint2*)(kb + (r * 72 + c) * 2) = hp;
                *(uint2*)(kb + 18432 + (r * 72 + c) * 2) = lp;
            }
        }
        __syncthreads();
    }

    // combine 4 column-quad partials per row
    float* smm = (float*)(smc + SC_STATS);
    float* sml = smm + 512;
    if (tg == 0) {
#pragma unroll
        for (int mt = 0; mt < 2; mt++) {
            int rr = r1 + mt * 16;
            smm[wq * 128 + rr] = mA[mt];      sml[wq * 128 + rr] = lA[mt];
            smm[wq * 128 + rr + 8] = mB[mt];  sml[wq * 128 + rr + 8] = lB[mt];
        }
    }
    __syncthreads();
    if (tid < 128) {
        float M = smm[tid];
#pragma unroll
        for (int qd = 1; qd < 4; qd++) M = fmaxf(M, smm[qd * 128 + tid]);
        float L = 0.f;
#pragma unroll
        for (int qd = 0; qd < 4; qd++) L += sml[qd * 128 + tid] * ex2f(smm[qd * 128 + tid] - M);
        int base = hb * SEQ + qt * 128;
        g_m[base + tid] = M;
        g_l[base + tid] = L;
    }
}

// ==================== kernel 3: normalize + PV via f16-3x mma.sync ====================
// 512 threads; double-buffered smem; warp = (wr 0..7 rows of 16, wc 0..1 col half of 32)
#define PV_PBUF 55296
#define PV_STAT 110592
#define PV_SMEM_BYTES 111616

__global__ __launch_bounds__(512, 1) void pv_mma_kernel(float* __restrict__ attn) {
    extern __shared__ char smc[];
    uint32_t sb = su32(smc);
    float* msm  = (float*)(smc + PV_STAT);
    float* ilsm = (float*)(smc + PV_STAT + 512);

    int tid = threadIdx.x, lane = tid & 31, w = tid >> 5;
    int g = lane >> 2, tg = lane & 3;
    int wr = w & 7, wc = w >> 3;
    int hb = blockIdx.x, qt = blockIdx.y;

    if (tid < 128) {
        msm[tid] = g_m[hb * SEQ + qt * 128 + tid];
        ilsm[tid] = 1.0f / g_l[hb * SEQ + qt * 128 + tid];
    }
    __syncthreads();

    float* arow = attn + (size_t)hb * SEQ * SEQ + (size_t)(qt * 128) * SEQ;
    float C[4][4];
#pragma unroll
    for (int j = 0; j < 4; j++) { C[j][0] = C[j][1] = C[j][2] = C[j][3] = 0.f; }

    float4 aR[4], vR[2];
    // prologue: load + process chunk 0 into buf 0
    {
        const float* Vp = g_Vh + ((size_t)hb * SEQ) * DHEAD;
#pragma unroll
        for (int t = 0; t < 4; t++) {
            int f = tid + t * 512;
            int r = f >> 4, c = (f & 15) << 2;
            aR[t] = *(const float4*)(arow + (size_t)r * SEQ + c);
        }
#pragma unroll
        for (int t = 0; t < 2; t++) {
            int f = tid + t * 512;
            int kk = f >> 4, dd = (f & 15) << 2;
            vR[t] = *(const float4*)(Vp + (size_t)kk * DHEAD + dd);
        }
        char* bufc = smc;
#pragma unroll
        for (int t = 0; t < 4; t++) {
            int f = tid + t * 512;
            int r = f >> 4, c = (f & 15) << 2;
            float4 v = aR[t];
            float mm = msm[r], il = ilsm[r];
            v.x = ex2f(v.x - mm) * il; v.y = ex2f(v.y - mm) * il;
            v.z = ex2f(v.z - mm) * il; v.w = ex2f(v.w - mm) * il;
            *(float4*)(arow + (size_t)r * SEQ + c) = v;
            uint2 hp, lp;
            h2split(v, hp, lp);
            *(uint2*)(bufc + (r * 72 + c) * 2) = hp;
            *(uint2*)(bufc + 18432 + (r * 72 + c) * 2) = lp;
        }
#pragma unroll
        for (int t = 0; t < 2; t++) {
            int f = tid + t * 512;
            int kk = f >> 4, dd = (f & 15) << 2;
            uint2 hp, lp;
            h2split(vR[t], hp, lp);
            *(uint2*)(bufc + 36864 + (kk * 72 + dd) * 2) = hp;
            *(uint2*)(bufc + 46080 + (kk * 72 + dd) * 2) = lp;
        }
    }
    __syncthreads();

    int arw = wr * 16 + (lane & 15);
    int acl = ((lane >> 4) & 1) * 8;

    for (int kc = 0; kc < 32; kc++) {
        int b = kc & 1;
        if (kc < 31) {
            const float* Vp = g_Vh + ((size_t)hb * SEQ + (kc + 1) * 64) * DHEAD;
#pragma unroll
            for (int t = 0; t < 4; t++) {
                int f = tid + t * 512;
                int r = f >> 4, c = (f & 15) << 2;
                aR[t] = *(const float4*)(arow + (size_t)r * SEQ + (kc + 1) * 64 + c);
            }
#pragma unroll
            for (int t = 0; t < 2; t++) {
                int f = tid + t * 512;
                int kk = f >> 4, dd = (f & 15) << 2;
                vR[t] = *(const float4*)(Vp + (size_t)kk * DHEAD + dd);
            }
        }
        // mma from buffer b
        uint32_t bufb = sb + b * PV_PBUF;
        uint32_t aHf[4][4], aLf[4][4];
#pragma unroll
        for (int s = 0; s < 4; s++) {
            uint32_t off = (uint32_t)((arw * 72 + s * 16 + acl) * 2);
            ldmA(aHf[s], bufb + off);
            ldmA(aLf[s], bufb + 18432 + off);
        }
#pragma unroll
        for (int j = 0; j < 4; j++) {
#pragma unroll
            for (int s = 0; s < 4; s++) {
                uint32_t bH[2], bL[2];
                uint32_t off = (uint32_t)(((s * 16 + (lane & 15)) * 72 + wc * 32 + j * 8) * 2);
                ldmB(bH, bufb + 36864 + off);
                ldmB(bL, bufb + 46080 + off);
                mma_f16(C[j], aHf[s], bH);
                mma_f16(C[j], aHf[s], bL);
                mma_f16(C[j], aLf[s], bH);
            }
        }
        if (kc < 31) {
            char* bufc = smc + (b ^ 1) * PV_PBUF;
#pragma unroll
            for (int t = 0; t < 4; t++) {
                int f = tid + t * 512;
                int r = f >> 4, c = (f & 15) << 2;
                float4 v = aR[t];
                float mm = msm[r], il = ilsm[r];
                v.x = ex2f(v.x - mm) * il; v.y = ex2f(v.y - mm) * il;
                v.z = ex2f(v.z - mm) * il; v.w = ex2f(v.w - mm) * il;
                *(float4*)(arow + (size_t)r * SEQ + (kc + 1) * 64 + c) = v;
                uint2 hp, lp;
                h2split(v, hp, lp);
                *(uint2*)(bufc + (r * 72 + c) * 2) = hp;
                *(uint2*)(bufc + 18432 + (r * 72 + c) * 2) = lp;
            }
#pragma unroll
            for (int t = 0; t < 2; t++) {
                int f = tid + t * 512;
                int kk = f >> 4, dd = (f & 15) << 2;
                uint2 hp, lp;
                h2split(vR[t], hp, lp);
                *(uint2*)(bufc + 36864 + (kk * 72 + dd) * 2) = hp;
                *(uint2*)(bufc + 46080 + (kk * 72 + dd) * 2) = lp;
            }
        }
        __syncthreads();
    }

    int h = hb >> 1, bb = hb & 1;
    int r1 = wr * 16 + g;
    float* o1 = g_oh + ((size_t)(bb * SEQ + qt * 128 + r1)) * HD + h * 64 + wc * 32 + 2 * tg;
    float* o2 = o1 + 8 * HD;
#pragma unroll
    for (int j = 0; j < 4; j++) {
        *(float2*)(o1 + j * 8) = make_float2(C[j][0], C[j][1]);
        *(float2*)(o2 + j * 8) = make_float2(C[j][2], C[j][3]);
    }
}

// ==================== kernel 4: out projection via f16-3x mma.sync ====================
// 512 threads; double-buffered; warp = (wr 0..7 rows of 16, wc 0..1 col half of 64)
#define OP_PBUF 71680
#define OP_SMEM_BYTES 143360

__global__ __launch_bounds__(512, 1) void oproj_mma_kernel(
    const float* __restrict__ Wo, const float* __restrict__ bo, float* __restrict__ out) {
    extern __shared__ char smc[];
    uint32_t sb = su32(smc);

    int tid = threadIdx.x, lane = tid & 31, w = tid >> 5;
    int g = lane >> 2, tg = lane & 3;
    int wr = w & 7, wc = w >> 3;
    int rt = blockIdx.x, ct = blockIdx.y;

    float C[8][4];
#pragma unroll
    for (int j = 0; j < 8; j++) { C[j][0] = C[j][1] = C[j][2] = C[j][3] = 0.f; }

    float4 aR[4], bR[4];
    // prologue
    {
#pragma unroll
        for (int t = 0; t < 4; t++) {
            int f = tid + t * 512;
            int r = f >> 4, c = (f & 15) << 2;
            aR[t] = *(const float4*)(g_oh + (size_t)(rt * 128 + r) * HD + c);
        }
#pragma unroll
        for (int t = 0; t < 4; t++) {
            int f = tid + t * 512;
            int kk = f >> 5, nn = (f & 31) << 2;
            bR[t] = *(const float4*)(Wo + (size_t)kk * DO + ct * 128 + nn);
        }
        char* bufc = smc;
#pragma unroll
        for (int t = 0; t < 4; t++) {
            int f = tid + t * 512;
            int r = f >> 4, c = (f & 15) << 2;
            uint2 hp, lp;
            h2split(aR[t], hp, lp);
            *(uint2*)(bufc + (r * 72 + c) * 2) = hp;
            *(uint2*)(bufc + 18432 + (r * 72 + c) * 2) = lp;
        }
#pragma unroll
        for (int t = 0; t < 4; t++) {
            int f = tid + t * 512;
            int kk = f >> 5, nn = (f & 31) << 2;
            uint2 hp, lp;
            h2split(bR[t], hp, lp);
            *(uint2*)(bufc + 36864 + (kk * 136 + nn) * 2) = hp;
            *(uint2*)(bufc + 54272 + (kk * 136 + nn) * 2) = lp;
        }
    }
    __syncthreads();

    int arw = wr * 16 + (lane & 15);
    int acl = ((lane >> 4) & 1) * 8;

    for (int kc = 0; kc < 16; kc++) {
        int b = kc & 1;
        if (kc < 15) {
#pragma unroll
            for (int t = 0; t < 4; t++) {
                int f = tid + t * 512;
                int r = f >> 4, c = (f & 15) << 2;
                aR[t] = *(const float4*)(g_oh + (size_t)(rt * 128 + r) * HD + (kc + 1) * 64 + c);
            }
#pragma unroll
            for (int t = 0; t < 4; t++) {
                int f = tid + t * 512;
                int kk = f >> 5, nn = (f & 31) << 2;
                bR[t] = *(const float4*)(Wo + (size_t)((kc + 1) * 64 + kk) * DO + ct * 128 + nn);
            }
        }
        uint32_t bufb = sb + b * OP_PBUF;
        uint32_t aHf[4][4], aLf[4][4];
#pragma unroll
        for (int s = 0; s < 4; s++) {
            uint32_t off = (uint32_t)((arw * 72 + s * 16 + acl) * 2);
            ldmA(aHf[s], bufb + off);
            ldmA(aLf[s], bufb + 18432 + off);
        }
#pragma unroll
        for (int j = 0; j < 8; j++) {
#pragma unroll
            for (int s = 0; s < 4; s++) {
                uint32_t bH[2], bL[2];
                uint32_t off = (uint32_t)(((s * 16 + (lane & 15)) * 136 + wc * 64 + j * 8) * 2);
                ldmB(bH, bufb + 36864 + off);
                ldmB(bL, bufb + 54272 + off);
                mma_f16(C[j], aHf[s], bH);
                mma_f16(C[j], aHf[s], bL);
                mma_f16(C[j], aLf[s], bH);
            }
        }
        if (kc < 15) {
            char* bufc = smc + (b ^ 1) * OP_PBUF;
#pragma unroll
            for (int t = 0; t < 4; t++) {
                int f = tid + t * 512;
                int r = f >> 4, c = (f & 15) << 2;
                uint2 hp, lp;
                h2split(aR[t], hp, lp);
                *(uint2*)(bufc + (r * 72 + c) * 2) = hp;
                *(uint2*)(bufc + 18432 + (r * 72 + c) * 2) = lp;
            }
#pragma unroll
            for (int t = 0; t < 4; t++) {
                int f = tid + t * 512;
                int kk = f >> 5, nn = (f & 31) << 2;
                uint2 hp, lp;
                h2split(bR[t], hp, lp);
                *(uint2*)(bufc + 36864 + (kk * 136 + nn) * 2) = hp;
                *(uint2*)(bufc + 54272 + (kk * 136 + nn) * 2) = lp;
            }
        }
        __syncthreads();
    }

    int r1 = wr * 16 + g;
    const float* bp = bo + ct * 128 + wc * 64;
    float* o1 = out + (size_t)(rt * 128 + r1) * DO + ct * 128 + wc * 64 + 2 * tg;
    float* o2 = o1 + 8 * DO;
#pragma unroll
    for (int j = 0; j < 8; j++) {
        int cc = j * 8 + 2 * tg;
        *(float2*)(o1 + j * 8) = make_float2(C[j][0] + bp[cc], C[j][1] + bp[cc + 1]);
        *(float2*)(o2 + j * 8) = make_float2(C[j][2] + bp[cc], C[j][3] + bp[cc + 1]);
    }
}

// ==================== launch ====================
extern "C" void kernel_launch(void* const* d_in, const int* in_sizes, int n_in,
                              void* d_out, int out_size) {
    const float* q  = (const float*)d_in[0];
    const float* k  = (const float*)d_in[1];
    const float* v  = (const float*)d_in[2];
    const float* Wq = (const float*)d_in[3];
    const float* bq = (const float*)d_in[4];
    const float* Wk = (const float*)d_in[5];
    const float* bk = (const float*)d_in[6];
    const float* Wv = (const float*)d_in[7];
    const float* bv = (const float*)d_in[8];
    const float* Wo = (const float*)d_in[9];
    const float* bo = (const float*)d_in[10];
    (void)in_sizes; (void)n_in;

    long long osz = (long long)out_size;
    float* attn = nullptr;
    float* out  = nullptr;
    if (osz >= ATTN_ELEMS + OUT_ELEMS) {
        attn = (float*)d_out;
        out  = (float*)d_out + ATTN_ELEMS;
    } else if (osz >= ATTN_ELEMS) {
        attn = (float*)d_out;
    } else {
        out = (float*)d_out;
    }
    if (!attn) cudaGetSymbolAddress((void**)&attn, g_attn_fb);

    float *Qh, *Kh, *Vh;
    cudaGetSymbolAddress((void**)&Qh, g_Qh);
    cudaGetSymbolAddress((void**)&Kh, g_Kh);
    cudaGetSymbolAddress((void**)&Vh, g_Vh);

    cudaFuncSetAttribute(scores_mma_kernel, cudaFuncAttributeMaxDynamicSharedMemorySize, SC_SMEM_BYTES);
    cudaFuncSetAttribute(pv_mma_kernel, cudaFuncAttributeMaxDynamicSharedMemorySize, PV_SMEM_BYTES);
    cudaFuncSetAttribute(oproj_mma_kernel, cudaFuncAttributeMaxDynamicSharedMemorySize, OP_SMEM_BYTES);

    proj_fused_kernel<<<dim3(64, 16, 3), 256>>>(q, k, v, Wq, bq, Wk, bk, Wv, bv, Qh, Kh, Vh);
    scores_mma_kernel<<<dim3(HB, 16), 512, SC_SMEM_BYTES>>>(attn);
    pv_mma_kernel<<<dim3(HB, 16), 512, PV_SMEM_BYTES>>>(attn);
    if (out) oproj_mma_kernel<<<dim3(32, 8), 512, OP_SMEM_BYTES>>>(Wo, bo, out);
}